// round 11
// baseline (speedup 1.0000x reference)
#include <cuda_runtime.h>
#include <cuda_bf16.h>

#define N_NODES 8192
#define D_IN    512
#define H1      32
#define H2      16
#define E_EDGES 262144
#define ELL_S   96            // padded row stride; deg ~ Binom(E,1/N): mean 32, sigma 5.7

typedef unsigned long long ull;

// -------- device-global scratch (no allocation allowed) --------
__device__ float g_xw0 [N_NODES * H1];     // X @ W0
__device__ float g_hw1 [N_NODES * H2];     // relu(spmm1) @ W1
__device__ float g_mean[N_NODES * H2];     // spmm2 result
__device__ int   g_cnt [N_NODES];          // per-row degree/cursor (re-zeroed in decode)
__device__ int2  g_ell [N_NODES * ELL_S];  // padded (col, val bits) rows

// packed fp32x2 helpers (sm_103a FFMA2, PTX-only)
__device__ __forceinline__ ull ffma2(ull a, ull b, ull c) {
    ull d;
    asm("fma.rn.f32x2 %0, %1, %2, %3;" : "=l"(d) : "l"(a), "l"(b), "l"(c));
    return d;
}
__device__ __forceinline__ ull pack2(float lo, float hi) {
    ull d;
    asm("mov.b64 %0, {%1, %2};" : "=l"(d) : "r"(__float_as_uint(lo)), "r"(__float_as_uint(hi)));
    return d;
}
__device__ __forceinline__ float hadd2(ull p) {
    unsigned lo, hi;
    asm("mov.b64 {%0, %1}, %2;" : "=r"(lo), "=r"(hi) : "l"(p));
    return __uint_as_float(lo) + __uint_as_float(hi);
}

// ===================== K1 (fused): xw0 GEMM + ELL scatter =====================
__global__ __launch_bounds__(512, 3) void k_phase1(const float* __restrict__ X,
                                                   const float* __restrict__ W0,
                                                   const int* __restrict__ erow,
                                                   const int* __restrict__ ecol,
                                                   const float* __restrict__ eval) {
    const int tid = threadIdx.x;

    if (blockIdx.x >= 1024) {
        // ---- ELL scatter: 4 edges/thread, 4 independent cursor-atomic chains
        int base = ((blockIdx.x - 1024) * 512 + tid) * 4;
        int4   r4 = *reinterpret_cast<const int4*>(&erow[base]);
        int4   c4 = *reinterpret_cast<const int4*>(&ecol[base]);
        float4 v4 = *reinterpret_cast<const float4*>(&eval[base]);
        int p0 = atomicAdd(&g_cnt[r4.x], 1);
        int p1 = atomicAdd(&g_cnt[r4.y], 1);
        int p2 = atomicAdd(&g_cnt[r4.z], 1);
        int p3 = atomicAdd(&g_cnt[r4.w], 1);
        g_ell[r4.x * ELL_S + p0] = make_int2(c4.x, __float_as_int(v4.x));
        g_ell[r4.y * ELL_S + p1] = make_int2(c4.y, __float_as_int(v4.y));
        g_ell[r4.z * ELL_S + p2] = make_int2(c4.z, __float_as_int(v4.z));
        g_ell[r4.w * ELL_S + p3] = make_int2(c4.w, __float_as_int(v4.w));
        return;
    }

    // ---- xw0: 16 warps; warp w owns k-slice [32w,32w+32), W pre-packed f32x2
    __shared__ float sbuf[8 * 512];     // 16KB: X tile, then partials
    const int lane = tid & 31;
    const int wid  = tid >> 5;
    const int row0 = blockIdx.x * 8;
    const int kw   = wid * 32;

    ull wp[16];
    #pragma unroll
    for (int kk = 0; kk < 16; kk++)
        wp[kk] = pack2(W0[(size_t)(kw + 2 * kk)     * H1 + lane],
                       W0[(size_t)(kw + 2 * kk + 1) * H1 + lane]);

    {
        const float4* X4 = reinterpret_cast<const float4*>(X + (size_t)row0 * D_IN);
        float4* S4 = reinterpret_cast<float4*>(sbuf);
        S4[tid]       = X4[tid];
        S4[tid + 512] = X4[tid + 512];
    }
    __syncthreads();

    ull acc2[8];
    #pragma unroll
    for (int r = 0; r < 8; r++) acc2[r] = 0ull;

    #pragma unroll
    for (int kk4 = 0; kk4 < 8; kk4++) {
        const int k = kw + kk4 * 4;
        const ull w01 = wp[kk4 * 2];
        const ull w23 = wp[kk4 * 2 + 1];
        #pragma unroll
        for (int r = 0; r < 8; r++) {
            ulonglong2 xq = *reinterpret_cast<const ulonglong2*>(&sbuf[r * 512 + k]);
            acc2[r] = ffma2(xq.x, w01, acc2[r]);
            acc2[r] = ffma2(xq.y, w23, acc2[r]);
        }
    }
    __syncthreads();
    #pragma unroll
    for (int r = 0; r < 8; r++)
        sbuf[wid * 256 + r * 32 + lane] = hadd2(acc2[r]);
    __syncthreads();

    if (tid < 256) {
        int r = tid >> 5, c = tid & 31;
        float s = 0.f;
        #pragma unroll
        for (int w = 0; w < 16; w++)
            s += sbuf[w * 256 + r * 32 + c];
        g_xw0[(size_t)(row0 + r) * H1 + c] = s;
    }
}

// ===================== K2: fused spmm1 + relu + @W1 (warp per row) =====================
__global__ void k_spmm1_hw1(const float* __restrict__ W1) {
    __shared__ float sW1[H1][H2];
    __shared__ float sH[8][H1];
    const int tid  = threadIdx.x;
    const int lane = tid & 31;
    const int wid  = tid >> 5;
    for (int idx = tid; idx < H1 * H2; idx += 256)
        sW1[idx >> 4][idx & 15] = W1[idx];
    __syncthreads();

    const int row = blockIdx.x * 8 + wid;
    const int beg = row * ELL_S;
    const int end = beg + g_cnt[row];
    float acc = 0.f;
    for (int e0 = beg; e0 < end; e0 += 32) {
        int ee = e0 + lane;
        int2 ed = (ee < end) ? g_ell[ee] : make_int2(0, 0);
        #pragma unroll
        for (int j = 0; j < 32; j++) {
            int   cj = __shfl_sync(0xFFFFFFFFu, ed.x, j);
            float vj = __int_as_float(__shfl_sync(0xFFFFFFFFu, ed.y, j));
            acc = fmaf(vj, g_xw0[cj * H1 + lane], acc);
        }
    }
    sH[wid][lane] = fmaxf(acc, 0.0f);
    __syncwarp();
    if (lane < H2) {
        float o = 0.f;
        #pragma unroll
        for (int k = 0; k < H1; k++)
            o = fmaf(sH[wid][k], sW1[k][lane], o);
        g_hw1[row * H2 + lane] = o;
    }
}

// ===================== K3: spmm2 (warp per row, half-warps on even/odd edges) =====================
__global__ void k_spmm2() {
    const int tid  = threadIdx.x;
    const int lane = tid & 31;
    const int wid  = tid >> 5;
    const int half = lane >> 4;
    const int col  = lane & 15;

    const int row = blockIdx.x * 8 + wid;
    const int beg = row * ELL_S;
    const int end = beg + g_cnt[row];
    float acc = 0.f;
    for (int e0 = beg; e0 < end; e0 += 32) {
        int ee = e0 + lane;
        int2 ed = (ee < end) ? g_ell[ee] : make_int2(0, 0);  // zero-filled tail
        #pragma unroll
        for (int j = 0; j < 16; j++) {
            int jj = j * 2 + half;
            int   cj = __shfl_sync(0xFFFFFFFFu, ed.x, jj);
            float vj = __int_as_float(__shfl_sync(0xFFFFFFFFu, ed.y, jj));
            acc = fmaf(vj, g_hw1[cj * H2 + col], acc);
        }
    }
    acc += __shfl_xor_sync(0xFFFFFFFFu, acc, 16);
    if (lane < H2) g_mean[row * H2 + lane] = acc;
}

// ===================== fast sigmoid: single MUFU tanh =====================
// Z >= 0 => x >= 0 => sigmoid(x) = 0.5*tanh(x/2) + 0.5, no cancellation.
__device__ __forceinline__ float fast_sigmoid(float x) {
    float th;
    asm("tanh.approx.f32 %0, %1;" : "=f"(th) : "f"(x * 0.5f));
    return fmaf(th, 0.5f, 0.5f);
}

// ===================== K4: decode A = sigmoid(Z Z^T), full grid =====================
// 128(i) x 64(j) tile per block, 256 thr, 8x4 per thread. No symmetry/transpose:
// every store is a straight coalesced STG.128 run; no smem epilogue, no barriers.
__global__ __launch_bounds__(256, 5) void k_decode(float* __restrict__ out) {
    __shared__ float sA[16 * 132];      // [k][i-row]
    __shared__ float sB[16 * 68];       // [k][j-row]
    const int tid = threadIdx.x;
    const int bj  = blockIdx.x;         // 128 j-tiles of 64
    const int bi  = blockIdx.y;         // 64  i-tiles of 128
    const int i0  = bi * 128, j0 = bj * 64;

    // re-zero g_cnt for the next graph replay (dead by now)
    if (bi == 0 && bj < 32) g_cnt[bj * 256 + tid] = 0;

    #pragma unroll
    for (int it = 0; it < 8; it++) {
        int idx = tid + it * 256;       // 128*16 elements
        int r = idx >> 4, c = idx & 15;
        sA[c * 132 + r] = fmaxf(g_mean[(i0 + r) * H2 + c], 1e-32f);
    }
    #pragma unroll
    for (int it = 0; it < 4; it++) {
        int idx = tid + it * 256;       // 64*16 elements
        int r = idx >> 4, c = idx & 15;
        sB[c * 68 + r] = fmaxf(g_mean[(j0 + r) * H2 + c], 1e-32f);
    }
    __syncthreads();

    const int tx = tid & 15;            // j-group: 4 cols
    const int ty = tid >> 4;            // i-group: 8 rows
    ull acc2[8][2];
    #pragma unroll
    for (int ii = 0; ii < 8; ii++) { acc2[ii][0] = 0ull; acc2[ii][1] = 0ull; }

    #pragma unroll
    for (int k = 0; k < H2; k++) {
        ulonglong2 bq = *reinterpret_cast<const ulonglong2*>(&sB[k * 68 + tx * 4]);
        float4 a0 = *reinterpret_cast<const float4*>(&sA[k * 132 + ty * 8]);
        float4 a1 = *reinterpret_cast<const float4*>(&sA[k * 132 + ty * 8 + 4]);
        float a[8] = {a0.x, a0.y, a0.z, a0.w, a1.x, a1.y, a1.z, a1.w};
        #pragma unroll
        for (int ii = 0; ii < 8; ii++) {
            ull ap = pack2(a[ii], a[ii]);
            acc2[ii][0] = ffma2(ap, bq.x, acc2[ii][0]);
            acc2[ii][1] = ffma2(ap, bq.y, acc2[ii][1]);
        }
    }

    #pragma unroll
    for (int ii = 0; ii < 8; ii++) {
        float v0, v1, v2, v3;
        {
            unsigned lo, hi;
            asm("mov.b64 {%0, %1}, %2;" : "=r"(lo), "=r"(hi) : "l"(acc2[ii][0]));
            v0 = fast_sigmoid(__uint_as_float(lo));
            v1 = fast_sigmoid(__uint_as_float(hi));
            asm("mov.b64 {%0, %1}, %2;" : "=r"(lo), "=r"(hi) : "l"(acc2[ii][1]));
            v2 = fast_sigmoid(__uint_as_float(lo));
            v3 = fast_sigmoid(__uint_as_float(hi));
        }
        int gi = i0 + ty * 8 + ii;
        float4 o = {v0, v1, v2, v3};
        __stcs(reinterpret_cast<float4*>(out + (size_t)gi * N_NODES + j0 + tx * 4), o);
    }
}

extern "C" void kernel_launch(void* const* d_in, const int* in_sizes, int n_in,
                              void* d_out, int out_size) {
    const float* X    = (const float*)d_in[0];
    const int*   erow = (const int*)  d_in[1];
    const int*   ecol = (const int*)  d_in[2];
    const float* ev   = (const float*)d_in[3];
    const float* W0   = (const float*)d_in[4];
    const float* W1   = (const float*)d_in[5];
    // d_in[6] (W2) unused: std branch is dead in eval (Z = mean)
    float* out = (float*)d_out;

    k_phase1  <<<1024 + 128, 512>>>(X, W0, erow, ecol, ev);   // xw0 ∥ scatter
    k_spmm1_hw1<<<N_NODES / 8, 256>>>(W1);
    k_spmm2   <<<N_NODES / 8, 256>>>();
    dim3 dgrid(128, 64);          // 128 j-tiles x 64 i-tiles
    k_decode  <<<dgrid, 256>>>(out);
}

// round 12
// speedup vs baseline: 2.1008x; 2.1008x over previous
#include <cuda_runtime.h>
#include <cuda_bf16.h>

#define N_NODES 8192
#define D_IN    512
#define H1      32
#define H2      16
#define E_EDGES 262144
#define ELL_S   96            // padded row stride; deg ~ Binom(E,1/N): mean 32, sigma 5.7

typedef unsigned long long ull;

// -------- device-global scratch (no allocation allowed) --------
__device__ float g_xw0 [N_NODES * H1];     // X @ W0
__device__ float g_hw1 [N_NODES * H2];     // relu(spmm1) @ W1
__device__ float g_mean[N_NODES * H2];     // spmm2 result
__device__ int   g_cnt [N_NODES];          // per-row degree/cursor (re-zeroed in decode)
__device__ int2  g_ell [N_NODES * ELL_S];  // padded (col, val bits) rows

// packed fp32x2 helpers (sm_103a FFMA2, PTX-only)
__device__ __forceinline__ ull ffma2(ull a, ull b, ull c) {
    ull d;
    asm("fma.rn.f32x2 %0, %1, %2, %3;" : "=l"(d) : "l"(a), "l"(b), "l"(c));
    return d;
}
__device__ __forceinline__ ull pack2(float lo, float hi) {
    ull d;
    asm("mov.b64 %0, {%1, %2};" : "=l"(d) : "r"(__float_as_uint(lo)), "r"(__float_as_uint(hi)));
    return d;
}
__device__ __forceinline__ float hadd2(ull p) {
    unsigned lo, hi;
    asm("mov.b64 {%0, %1}, %2;" : "=r"(lo), "=r"(hi) : "l"(p));
    return __uint_as_float(lo) + __uint_as_float(hi);
}

// ===================== K1 (fused): xw0 GEMM + ELL scatter =====================
__global__ __launch_bounds__(512, 3) void k_phase1(const float* __restrict__ X,
                                                   const float* __restrict__ W0,
                                                   const int* __restrict__ erow,
                                                   const int* __restrict__ ecol,
                                                   const float* __restrict__ eval) {
    const int tid = threadIdx.x;

    if (blockIdx.x >= 1024) {
        // ---- ELL scatter: 4 edges/thread, 4 independent cursor-atomic chains
        int base = ((blockIdx.x - 1024) * 512 + tid) * 4;
        int4   r4 = *reinterpret_cast<const int4*>(&erow[base]);
        int4   c4 = *reinterpret_cast<const int4*>(&ecol[base]);
        float4 v4 = *reinterpret_cast<const float4*>(&eval[base]);
        int p0 = atomicAdd(&g_cnt[r4.x], 1);
        int p1 = atomicAdd(&g_cnt[r4.y], 1);
        int p2 = atomicAdd(&g_cnt[r4.z], 1);
        int p3 = atomicAdd(&g_cnt[r4.w], 1);
        g_ell[r4.x * ELL_S + p0] = make_int2(c4.x, __float_as_int(v4.x));
        g_ell[r4.y * ELL_S + p1] = make_int2(c4.y, __float_as_int(v4.y));
        g_ell[r4.z * ELL_S + p2] = make_int2(c4.z, __float_as_int(v4.z));
        g_ell[r4.w * ELL_S + p3] = make_int2(c4.w, __float_as_int(v4.w));
        return;
    }

    // ---- xw0: 16 warps; warp w owns k-slice [32w,32w+32), W pre-packed f32x2
    __shared__ float sbuf[8 * 512];     // 16KB: X tile, then partials
    const int lane = tid & 31;
    const int wid  = tid >> 5;
    const int row0 = blockIdx.x * 8;
    const int kw   = wid * 32;

    ull wp[16];
    #pragma unroll
    for (int kk = 0; kk < 16; kk++)
        wp[kk] = pack2(W0[(size_t)(kw + 2 * kk)     * H1 + lane],
                       W0[(size_t)(kw + 2 * kk + 1) * H1 + lane]);

    {
        const float4* X4 = reinterpret_cast<const float4*>(X + (size_t)row0 * D_IN);
        float4* S4 = reinterpret_cast<float4*>(sbuf);
        S4[tid]       = X4[tid];
        S4[tid + 512] = X4[tid + 512];
    }
    __syncthreads();

    ull acc2[8];
    #pragma unroll
    for (int r = 0; r < 8; r++) acc2[r] = 0ull;

    #pragma unroll
    for (int kk4 = 0; kk4 < 8; kk4++) {
        const int k = kw + kk4 * 4;
        const ull w01 = wp[kk4 * 2];
        const ull w23 = wp[kk4 * 2 + 1];
        #pragma unroll
        for (int r = 0; r < 8; r++) {
            ulonglong2 xq = *reinterpret_cast<const ulonglong2*>(&sbuf[r * 512 + k]);
            acc2[r] = ffma2(xq.x, w01, acc2[r]);
            acc2[r] = ffma2(xq.y, w23, acc2[r]);
        }
    }
    __syncthreads();
    #pragma unroll
    for (int r = 0; r < 8; r++)
        sbuf[wid * 256 + r * 32 + lane] = hadd2(acc2[r]);
    __syncthreads();

    if (tid < 256) {
        int r = tid >> 5, c = tid & 31;
        float s = 0.f;
        #pragma unroll
        for (int w = 0; w < 16; w++)
            s += sbuf[w * 256 + r * 32 + c];
        g_xw0[(size_t)(row0 + r) * H1 + c] = s;
    }
}

// ===================== K2: fused spmm1 + relu + @W1 (warp per row) =====================
__global__ void k_spmm1_hw1(const float* __restrict__ W1) {
    __shared__ float sW1[H1][H2];
    __shared__ float sH[8][H1];
    const int tid  = threadIdx.x;
    const int lane = tid & 31;
    const int wid  = tid >> 5;
    for (int idx = tid; idx < H1 * H2; idx += 256)
        sW1[idx >> 4][idx & 15] = W1[idx];
    __syncthreads();

    const int row = blockIdx.x * 8 + wid;
    const int beg = row * ELL_S;
    const int end = beg + g_cnt[row];
    float acc = 0.f;
    for (int e0 = beg; e0 < end; e0 += 32) {
        int ee = e0 + lane;
        int2 ed = (ee < end) ? g_ell[ee] : make_int2(0, 0);
        #pragma unroll
        for (int j = 0; j < 32; j++) {
            int   cj = __shfl_sync(0xFFFFFFFFu, ed.x, j);
            float vj = __int_as_float(__shfl_sync(0xFFFFFFFFu, ed.y, j));
            acc = fmaf(vj, g_xw0[cj * H1 + lane], acc);
        }
    }
    sH[wid][lane] = fmaxf(acc, 0.0f);
    __syncwarp();
    if (lane < H2) {
        float o = 0.f;
        #pragma unroll
        for (int k = 0; k < H1; k++)
            o = fmaf(sH[wid][k], sW1[k][lane], o);
        g_hw1[row * H2 + lane] = o;
    }
}

// ===================== K3: spmm2 (warp per row, half-warps on even/odd edges) =====================
__global__ void k_spmm2() {
    const int tid  = threadIdx.x;
    const int lane = tid & 31;
    const int wid  = tid >> 5;
    const int half = lane >> 4;
    const int col  = lane & 15;

    const int row = blockIdx.x * 8 + wid;
    const int beg = row * ELL_S;
    const int end = beg + g_cnt[row];
    float acc = 0.f;
    for (int e0 = beg; e0 < end; e0 += 32) {
        int ee = e0 + lane;
        int2 ed = (ee < end) ? g_ell[ee] : make_int2(0, 0);  // zero-filled tail
        #pragma unroll
        for (int j = 0; j < 16; j++) {
            int jj = j * 2 + half;
            int   cj = __shfl_sync(0xFFFFFFFFu, ed.x, jj);
            float vj = __int_as_float(__shfl_sync(0xFFFFFFFFu, ed.y, jj));
            acc = fmaf(vj, g_hw1[cj * H2 + col], acc);
        }
    }
    acc += __shfl_xor_sync(0xFFFFFFFFu, acc, 16);
    if (lane < H2) g_mean[row * H2 + lane] = acc;
}

// ===================== fast sigmoid: single MUFU tanh =====================
// Z >= 0 => x >= 0 => sigmoid(x) = 0.5*tanh(x/2) + 0.5, no cancellation.
__device__ __forceinline__ float fast_sigmoid(float x) {
    float th;
    asm("tanh.approx.f32 %0, %1;" : "=f"(th) : "f"(x * 0.5f));
    return fmaf(th, 0.5f, 0.5f);
}

// ===================== K4: decode A = sigmoid(Z Z^T), triangular =====================
// 512 thr, per-thread 8(i)x4(j). Accumulate on i-PAIRS (a-pairs come straight
// from LDS.128, only 4 b-packs/k). Mirror via 4 chunked smem transposes with an
// XOR swizzle (group ^= (row>>2)&7) making the STS phase bank-conflict-free.
__global__ __launch_bounds__(512, 2) void k_decode(float* __restrict__ out) {
    __shared__ float smem[32 * 132];    // sA[16][132] | sB[16][132]; reused as transpose buf
    float* sA = smem;                   // [k][i-row], stride 132
    float* sB = smem + 16 * 132;

    const int t   = blockIdx.x;
    const int tid = threadIdx.x;

    // re-zero g_cnt for the next graph replay (dead by now)
    if (t < 16) g_cnt[t * 512 + tid] = 0;

    int i = (int)((sqrtf(8.0f * (float)t + 1.0f) - 1.0f) * 0.5f);
    int j = t - ((i * (i + 1)) >> 1);
    if (j < 0)  { i--; j = t - ((i * (i + 1)) >> 1); }
    if (j > i)  { i++; j = t - ((i * (i + 1)) >> 1); }
    const int bi = j, bj = i;
    const int i0 = bi * 128, j0 = bj * 128;

    for (int idx = tid; idx < 128 * H2; idx += 512) {
        int r = idx >> 4, c = idx & 15;
        sA[c * 132 + r] = fmaxf(g_mean[(i0 + r) * H2 + c], 1e-32f);
        sB[c * 132 + r] = fmaxf(g_mean[(j0 + r) * H2 + c], 1e-32f);
    }
    __syncthreads();

    const int tx = tid & 31;            // 4 j-cols each (tx*4)
    const int ty = tid >> 5;            // 8 i-rows each (ty*8)
    ull acc2[4][4];                     // [i-pair][j]
    #pragma unroll
    for (int p = 0; p < 4; p++)
        #pragma unroll
        for (int jj = 0; jj < 4; jj++) acc2[p][jj] = 0ull;

    #pragma unroll
    for (int k = 0; k < H2; k++) {
        ulonglong2 aq0 = *reinterpret_cast<const ulonglong2*>(&sA[k * 132 + ty * 8]);
        ulonglong2 aq1 = *reinterpret_cast<const ulonglong2*>(&sA[k * 132 + ty * 8 + 4]);
        float4 bv = *reinterpret_cast<const float4*>(&sB[k * 132 + tx * 4]);
        ull ap[4] = {aq0.x, aq0.y, aq1.x, aq1.y};      // i-pairs, no packing needed
        ull bp[4] = {pack2(bv.x, bv.x), pack2(bv.y, bv.y),
                     pack2(bv.z, bv.z), pack2(bv.w, bv.w)};
        #pragma unroll
        for (int p = 0; p < 4; p++)
            #pragma unroll
            for (int jj = 0; jj < 4; jj++)
                acc2[p][jj] = ffma2(ap[p], bp[jj], acc2[p][jj]);
    }

    // sigmoid -> accf[i-row][j]
    float accf[8][4];
    #pragma unroll
    for (int p = 0; p < 4; p++)
        #pragma unroll
        for (int jj = 0; jj < 4; jj++) {
            unsigned lo, hi;
            asm("mov.b64 {%0, %1}, %2;" : "=r"(lo), "=r"(hi) : "l"(acc2[p][jj]));
            accf[2 * p + 0][jj] = fast_sigmoid(__uint_as_float(lo));
            accf[2 * p + 1][jj] = fast_sigmoid(__uint_as_float(hi));
        }

    // normal tile (bi,bj): warp = 32 consecutive float4 = 512B per row — coalesced
    #pragma unroll
    for (int ii = 0; ii < 8; ii++) {
        int gi = i0 + ty * 8 + ii;
        float4 o = {accf[ii][0], accf[ii][1], accf[ii][2], accf[ii][3]};
        __stcs(reinterpret_cast<float4*>(out + (size_t)gi * N_NODES + j0 + tx * 4), o);
    }

    // mirror tile (bj,bi): 4 chunks of 32 j-rows, XOR-swizzled smem transpose
    if (bi != bj) {
        #pragma unroll 1
        for (int c = 0; c < 4; c++) {
            __syncthreads();            // prior smem readers done
            if ((tx >> 3) == c) {
                int txl = tx & 7;       // salt = (row>>2)&7 = txl (rows txl*4+jj)
                #pragma unroll
                for (int jj = 0; jj < 4; jj++) {
                    int row = txl * 4 + jj;
                    #pragma unroll
                    for (int ii = 0; ii < 8; ii++) {
                        int g = (2 * ty + (ii >> 2)) ^ txl;   // swizzled float4-group
                        smem[row * 132 + g * 4 + (ii & 3)] = accf[ii][jj];
                    }
                }
            }
            __syncthreads();
            #pragma unroll
            for (int it = 0; it < 2; it++) {
                int idx = tid + it * 512;
                int r  = idx >> 5;      // 0..31 (warp-uniform)
                int c4 = idx & 31;      // 0..31
                int g  = c4 ^ ((r >> 2) & 7);   // unswizzle: smem group c4 holds out-group g? no:
                // stored out-group G at smem group G^salt; reading smem group c4 -> out-group c4^salt = g
                float4 v = *reinterpret_cast<const float4*>(&smem[r * 132 + c4 * 4]);
                __stcs(reinterpret_cast<float4*>(
                    out + (size_t)(j0 + c * 32 + r) * N_NODES + i0 + g * 4), v);
            }
        }
    }
}

extern "C" void kernel_launch(void* const* d_in, const int* in_sizes, int n_in,
                              void* d_out, int out_size) {
    const float* X    = (const float*)d_in[0];
    const int*   erow = (const int*)  d_in[1];
    const int*   ecol = (const int*)  d_in[2];
    const float* ev   = (const float*)d_in[3];
    const float* W0   = (const float*)d_in[4];
    const float* W1   = (const float*)d_in[5];
    // d_in[6] (W2) unused: std branch is dead in eval (Z = mean)
    float* out = (float*)d_out;

    k_phase1  <<<1024 + 128, 512>>>(X, W0, erow, ecol, ev);   // xw0 ∥ scatter
    k_spmm1_hw1<<<N_NODES / 8, 256>>>(W1);
    k_spmm2   <<<N_NODES / 8, 256>>>();
    const int NT = 64 * 65 / 2;   // 2080 triangular tiles
    k_decode  <<<NT, 512>>>(out);
}

// round 13
// speedup vs baseline: 2.3718x; 1.1290x over previous
#include <cuda_runtime.h>
#include <cuda_bf16.h>

#define N_NODES 8192
#define D_IN    512
#define H1      32
#define H2      16
#define E_EDGES 262144
#define ELL_S   96            // padded row stride; deg ~ Binom(E,1/N): mean 32, sigma 5.7

typedef unsigned long long ull;

// -------- device-global scratch (no allocation allowed) --------
__device__ float g_xw0 [N_NODES * H1];     // X @ W0
__device__ float g_hw1 [N_NODES * H2];     // relu(spmm1) @ W1
__device__ float g_mean[N_NODES * H2];     // spmm2 result
__device__ int   g_cnt [N_NODES];          // per-row degree/cursor (re-zeroed in decode)
__device__ int2  g_ell [N_NODES * ELL_S];  // padded (col, val bits) rows

// packed fp32x2 helpers (sm_103a FFMA2, PTX-only)
__device__ __forceinline__ ull ffma2(ull a, ull b, ull c) {
    ull d;
    asm("fma.rn.f32x2 %0, %1, %2, %3;" : "=l"(d) : "l"(a), "l"(b), "l"(c));
    return d;
}
__device__ __forceinline__ ull pack2(float lo, float hi) {
    ull d;
    asm("mov.b64 %0, {%1, %2};" : "=l"(d) : "r"(__float_as_uint(lo)), "r"(__float_as_uint(hi)));
    return d;
}
__device__ __forceinline__ float2 u2f2(ull p) {
    float2 f;
    asm("mov.b64 {%0, %1}, %2;" : "=f"(f.x), "=f"(f.y) : "l"(p));
    return f;
}
__device__ __forceinline__ float hadd2(ull p) {
    float2 f = u2f2(p);
    return f.x + f.y;
}

// ===================== K1 (fused): xw0 GEMM + ELL scatter =====================
__global__ __launch_bounds__(512, 3) void k_phase1(const float* __restrict__ X,
                                                   const float* __restrict__ W0,
                                                   const int* __restrict__ erow,
                                                   const int* __restrict__ ecol,
                                                   const float* __restrict__ eval) {
    const int tid = threadIdx.x;

    if (blockIdx.x >= 1024) {
        // ---- ELL scatter: 4 edges/thread, 4 independent cursor-atomic chains
        int base = ((blockIdx.x - 1024) * 512 + tid) * 4;
        int4   r4 = *reinterpret_cast<const int4*>(&erow[base]);
        int4   c4 = *reinterpret_cast<const int4*>(&ecol[base]);
        float4 v4 = *reinterpret_cast<const float4*>(&eval[base]);
        int p0 = atomicAdd(&g_cnt[r4.x], 1);
        int p1 = atomicAdd(&g_cnt[r4.y], 1);
        int p2 = atomicAdd(&g_cnt[r4.z], 1);
        int p3 = atomicAdd(&g_cnt[r4.w], 1);
        g_ell[r4.x * ELL_S + p0] = make_int2(c4.x, __float_as_int(v4.x));
        g_ell[r4.y * ELL_S + p1] = make_int2(c4.y, __float_as_int(v4.y));
        g_ell[r4.z * ELL_S + p2] = make_int2(c4.z, __float_as_int(v4.z));
        g_ell[r4.w * ELL_S + p3] = make_int2(c4.w, __float_as_int(v4.w));
        return;
    }

    // ---- xw0: 16 warps; warp w owns k-slice [32w,32w+32), W pre-packed f32x2
    __shared__ float sbuf[8 * 512];     // 16KB: X tile, then partials
    const int lane = tid & 31;
    const int wid  = tid >> 5;
    const int row0 = blockIdx.x * 8;
    const int kw   = wid * 32;

    ull wp[16];
    #pragma unroll
    for (int kk = 0; kk < 16; kk++)
        wp[kk] = pack2(W0[(size_t)(kw + 2 * kk)     * H1 + lane],
                       W0[(size_t)(kw + 2 * kk + 1) * H1 + lane]);

    {
        const float4* X4 = reinterpret_cast<const float4*>(X + (size_t)row0 * D_IN);
        float4* S4 = reinterpret_cast<float4*>(sbuf);
        S4[tid]       = X4[tid];
        S4[tid + 512] = X4[tid + 512];
    }
    __syncthreads();

    ull acc2[8];
    #pragma unroll
    for (int r = 0; r < 8; r++) acc2[r] = 0ull;

    #pragma unroll
    for (int kk4 = 0; kk4 < 8; kk4++) {
        const int k = kw + kk4 * 4;
        const ull w01 = wp[kk4 * 2];
        const ull w23 = wp[kk4 * 2 + 1];
        #pragma unroll
        for (int r = 0; r < 8; r++) {
            ulonglong2 xq = *reinterpret_cast<const ulonglong2*>(&sbuf[r * 512 + k]);
            acc2[r] = ffma2(xq.x, w01, acc2[r]);
            acc2[r] = ffma2(xq.y, w23, acc2[r]);
        }
    }
    __syncthreads();
    #pragma unroll
    for (int r = 0; r < 8; r++)
        sbuf[wid * 256 + r * 32 + lane] = hadd2(acc2[r]);
    __syncthreads();

    if (tid < 256) {
        int r = tid >> 5, c = tid & 31;
        float s = 0.f;
        #pragma unroll
        for (int w = 0; w < 16; w++)
            s += sbuf[w * 256 + r * 32 + c];
        g_xw0[(size_t)(row0 + r) * H1 + c] = s;
    }
}

// ===================== K2: fused spmm1 + relu + @W1 =====================
// warp per row, HALF-warp per edge: lane = (edge parity, column pair).
// 16 iters per 32-edge tile, LDG.64 gathers + FFMA2, 2 edges in flight.
__global__ void k_spmm1_hw1(const float* __restrict__ W1) {
    __shared__ float sW1[H1][H2];
    __shared__ float sH[8][H1];
    const int tid  = threadIdx.x;
    const int lane = tid & 31;
    const int wid  = tid >> 5;
    const int half = lane >> 4;        // edge parity
    const int cp   = lane & 15;        // column pair (2 of H1=32)
    for (int idx = tid; idx < H1 * H2; idx += 256)
        sW1[idx >> 4][idx & 15] = W1[idx];
    __syncthreads();

    const int row = blockIdx.x * 8 + wid;
    const int beg = row * ELL_S;
    const int end = beg + g_cnt[row];
    ull acc = 0ull;
    for (int e0 = beg; e0 < end; e0 += 32) {
        int ee = e0 + lane;
        int2 ed = (ee < end) ? g_ell[ee] : make_int2(0, 0);  // zero-filled tail
        #pragma unroll
        for (int j = 0; j < 16; j++) {
            int jj = j * 2 + half;
            int   cj = __shfl_sync(0xFFFFFFFFu, ed.x, jj);
            float vj = __int_as_float(__shfl_sync(0xFFFFFFFFu, ed.y, jj));
            ull xv = *reinterpret_cast<const ull*>(&g_xw0[cj * H1 + 2 * cp]);
            acc = ffma2(pack2(vj, vj), xv, acc);
        }
    }
    float2 f = u2f2(acc);
    f.x += __shfl_xor_sync(0xFFFFFFFFu, f.x, 16);
    f.y += __shfl_xor_sync(0xFFFFFFFFu, f.y, 16);
    if (lane < 16) {
        sH[wid][2 * cp + 0] = fmaxf(f.x, 0.0f);
        sH[wid][2 * cp + 1] = fmaxf(f.y, 0.0f);
    }
    __syncwarp();
    if (lane < H2) {
        float o = 0.f;
        #pragma unroll
        for (int k = 0; k < H1; k++)
            o = fmaf(sH[wid][k], sW1[k][lane], o);
        g_hw1[row * H2 + lane] = o;
    }
}

// ===================== K3: spmm2: warp per row, QUARTER-warp per edge =====================
// 8 iters per 32-edge tile, 4 edges in flight, LDG.64 + FFMA2.
__global__ void k_spmm2() {
    const int tid  = threadIdx.x;
    const int lane = tid & 31;
    const int wid  = tid >> 5;
    const int q    = lane >> 3;        // edge phase 0..3
    const int cp   = lane & 7;         // column pair (2 of H2=16)

    const int row = blockIdx.x * 8 + wid;
    const int beg = row * ELL_S;
    const int end = beg + g_cnt[row];
    ull acc = 0ull;
    for (int e0 = beg; e0 < end; e0 += 32) {
        int ee = e0 + lane;
        int2 ed = (ee < end) ? g_ell[ee] : make_int2(0, 0);  // zero-filled tail
        #pragma unroll
        for (int j = 0; j < 8; j++) {
            int jj = j * 4 + q;
            int   cj = __shfl_sync(0xFFFFFFFFu, ed.x, jj);
            float vj = __int_as_float(__shfl_sync(0xFFFFFFFFu, ed.y, jj));
            ull hv = *reinterpret_cast<const ull*>(&g_hw1[cj * H2 + 2 * cp]);
            acc = ffma2(pack2(vj, vj), hv, acc);
        }
    }
    float2 f = u2f2(acc);
    f.x += __shfl_xor_sync(0xFFFFFFFFu, f.x, 8);
    f.y += __shfl_xor_sync(0xFFFFFFFFu, f.y, 8);
    f.x += __shfl_xor_sync(0xFFFFFFFFu, f.x, 16);
    f.y += __shfl_xor_sync(0xFFFFFFFFu, f.y, 16);
    if (lane < 8)
        *reinterpret_cast<float2*>(&g_mean[row * H2 + 2 * cp]) = f;
}

// ===================== fast sigmoid: single MUFU tanh =====================
// Z >= 0 => x >= 0 => sigmoid(x) = 0.5*tanh(x/2) + 0.5, no cancellation.
__device__ __forceinline__ float fast_sigmoid(float x) {
    float th;
    asm("tanh.approx.f32 %0, %1;" : "=f"(th) : "f"(x * 0.5f));
    return fmaf(th, 0.5f, 0.5f);
}

// ===================== K4: decode A = sigmoid(Z Z^T), triangular =====================
// 512 thr, per-thread 8(i)x4(j). Sigmoid applied IN PLACE into acc2 (no second
// register array). Mirror via 2 chunked smem transposes (64 j-rows each, XOR
// swizzle) -> 4 barriers total.
__global__ __launch_bounds__(512, 2) void k_decode(float* __restrict__ out) {
    __shared__ float smem[64 * 132];    // load: sA[16][132]|sB[16][132]; mirror: 64x132
    float* sA = smem;                   // [k][i-row], stride 132
    float* sB = smem + 16 * 132;

    const int t   = blockIdx.x;
    const int tid = threadIdx.x;

    // re-zero g_cnt for the next graph replay (dead by now)
    if (t < 16) g_cnt[t * 512 + tid] = 0;

    int i = (int)((sqrtf(8.0f * (float)t + 1.0f) - 1.0f) * 0.5f);
    int j = t - ((i * (i + 1)) >> 1);
    if (j < 0)  { i--; j = t - ((i * (i + 1)) >> 1); }
    if (j > i)  { i++; j = t - ((i * (i + 1)) >> 1); }
    const int bi = j, bj = i;
    const int i0 = bi * 128, j0 = bj * 128;

    for (int idx = tid; idx < 128 * H2; idx += 512) {
        int r = idx >> 4, c = idx & 15;
        sA[c * 132 + r] = fmaxf(g_mean[(i0 + r) * H2 + c], 1e-32f);
        sB[c * 132 + r] = fmaxf(g_mean[(j0 + r) * H2 + c], 1e-32f);
    }
    __syncthreads();

    const int tx = tid & 31;            // 4 j-cols each (tx*4)
    const int ty = tid >> 5;            // 8 i-rows each (ty*8)
    ull acc2[4][4];                     // [i-pair][j]
    #pragma unroll
    for (int p = 0; p < 4; p++)
        #pragma unroll
        for (int jj = 0; jj < 4; jj++) acc2[p][jj] = 0ull;

    #pragma unroll
    for (int k = 0; k < H2; k++) {
        ulonglong2 aq0 = *reinterpret_cast<const ulonglong2*>(&sA[k * 132 + ty * 8]);
        ulonglong2 aq1 = *reinterpret_cast<const ulonglong2*>(&sA[k * 132 + ty * 8 + 4]);
        float4 bv = *reinterpret_cast<const float4*>(&sB[k * 132 + tx * 4]);
        ull ap[4] = {aq0.x, aq0.y, aq1.x, aq1.y};      // i-pairs, no packing needed
        ull bp[4] = {pack2(bv.x, bv.x), pack2(bv.y, bv.y),
                     pack2(bv.z, bv.z), pack2(bv.w, bv.w)};
        #pragma unroll
        for (int p = 0; p < 4; p++)
            #pragma unroll
            for (int jj = 0; jj < 4; jj++)
                acc2[p][jj] = ffma2(ap[p], bp[jj], acc2[p][jj]);
    }

    // sigmoid IN PLACE (keeps register peak at the 32-reg accumulator set)
    #pragma unroll
    for (int p = 0; p < 4; p++)
        #pragma unroll
        for (int jj = 0; jj < 4; jj++) {
            float2 f = u2f2(acc2[p][jj]);
            acc2[p][jj] = pack2(fast_sigmoid(f.x), fast_sigmoid(f.y));
        }

    // normal tile (bi,bj): warp = 32 consecutive float4 = 512B per row
    #pragma unroll
    for (int p = 0; p < 4; p++) {
        float2 c0 = u2f2(acc2[p][0]);
        float2 c1 = u2f2(acc2[p][1]);
        float2 c2 = u2f2(acc2[p][2]);
        float2 c3 = u2f2(acc2[p][3]);
        float4 o0 = {c0.x, c1.x, c2.x, c3.x};
        float4 o1 = {c0.y, c1.y, c2.y, c3.y};
        int gi = i0 + ty * 8 + 2 * p;
        __stcs(reinterpret_cast<float4*>(out + (size_t)gi       * N_NODES + j0 + tx * 4), o0);
        __stcs(reinterpret_cast<float4*>(out + (size_t)(gi + 1) * N_NODES + j0 + tx * 4), o1);
    }

    // mirror tile (bj,bi): 2 chunks of 64 j-rows, XOR-swizzled smem transpose
    if (bi != bj) {
        #pragma unroll 1
        for (int c = 0; c < 2; c++) {
            __syncthreads();            // prior smem readers / copy-out done
            if ((tx >> 4) == c) {
                int txl = tx & 15;      // local rows txl*4+jj in [0,64)
                int salt = txl & 7;     // == (row>>2)&7 for these rows
                #pragma unroll
                for (int jj = 0; jj < 4; jj++) {
                    int row = txl * 4 + jj;
                    #pragma unroll
                    for (int ii = 0; ii < 8; ii++) {
                        float2 f = u2f2(acc2[ii >> 1][jj]);
                        float v = (ii & 1) ? f.y : f.x;
                        int g = (2 * ty + (ii >> 2)) ^ salt;   // swizzled float4-group
                        smem[row * 132 + g * 4 + (ii & 3)] = v;
                    }
                }
            }
            __syncthreads();
            #pragma unroll
            for (int it = 0; it < 4; it++) {
                int idx = tid + it * 512;
                int r  = idx >> 5;      // 0..63 (warp-uniform)
                int c4 = idx & 31;      // 0..31
                int g  = c4 ^ ((r >> 2) & 7);   // unswizzle
                float4 v = *reinterpret_cast<const float4*>(&smem[r * 132 + c4 * 4]);
                __stcs(reinterpret_cast<float4*>(
                    out + (size_t)(j0 + c * 64 + r) * N_NODES + i0 + g * 4), v);
            }
        }
    }
}

extern "C" void kernel_launch(void* const* d_in, const int* in_sizes, int n_in,
                              void* d_out, int out_size) {
    const float* X    = (const float*)d_in[0];
    const int*   erow = (const int*)  d_in[1];
    const int*   ecol = (const int*)  d_in[2];
    const float* ev   = (const float*)d_in[3];
    const float* W0   = (const float*)d_in[4];
    const float* W1   = (const float*)d_in[5];
    // d_in[6] (W2) unused: std branch is dead in eval (Z = mean)
    float* out = (float*)d_out;

    k_phase1  <<<1024 + 128, 512>>>(X, W0, erow, ecol, ev);   // xw0 ∥ scatter
    k_spmm1_hw1<<<N_NODES / 8, 256>>>(W1);
    k_spmm2   <<<N_NODES / 8, 256>>>();
    const int NT = 64 * 65 / 2;   // 2080 triangular tiles
    k_decode  <<<NT, 512>>>(out);
}

// round 14
// speedup vs baseline: 2.6120x; 1.1013x over previous
#include <cuda_runtime.h>
#include <cuda_bf16.h>

#define N_NODES 8192
#define D_IN    512
#define H1      32
#define H2      16
#define E_EDGES 262144
#define ELL_S   96            // padded row stride; deg ~ Binom(E,1/N): mean 32, sigma 5.7

typedef unsigned long long ull;

// -------- device-global scratch (no allocation allowed) --------
__device__ float g_xw0 [N_NODES * H1];     // X @ W0
__device__ float g_hw1 [N_NODES * H2];     // relu(spmm1) @ W1
__device__ float g_mean[N_NODES * H2];     // spmm2 result
__device__ int   g_cnt [N_NODES];          // per-row degree/cursor (re-zeroed in decode)
__device__ int2  g_ell [N_NODES * ELL_S];  // padded (col, val bits) rows

// packed fp32x2 helpers (sm_103a FFMA2, PTX-only)
__device__ __forceinline__ ull ffma2(ull a, ull b, ull c) {
    ull d;
    asm("fma.rn.f32x2 %0, %1, %2, %3;" : "=l"(d) : "l"(a), "l"(b), "l"(c));
    return d;
}
__device__ __forceinline__ ull pack2(float lo, float hi) {
    ull d;
    asm("mov.b64 %0, {%1, %2};" : "=l"(d) : "r"(__float_as_uint(lo)), "r"(__float_as_uint(hi)));
    return d;
}
__device__ __forceinline__ float2 u2f2(ull p) {
    float2 f;
    asm("mov.b64 {%0, %1}, %2;" : "=f"(f.x), "=f"(f.y) : "l"(p));
    return f;
}
__device__ __forceinline__ float hadd2(ull p) {
    float2 f = u2f2(p);
    return f.x + f.y;
}

// ===================== K1 (fused): xw0 GEMM + ELL scatter =====================
__global__ __launch_bounds__(512, 3) void k_phase1(const float* __restrict__ X,
                                                   const float* __restrict__ W0,
                                                   const int* __restrict__ erow,
                                                   const int* __restrict__ ecol,
                                                   const float* __restrict__ eval) {
    const int tid = threadIdx.x;

    if (blockIdx.x >= 1024) {
        // ---- ELL scatter: 4 edges/thread, 4 independent cursor-atomic chains
        int base = ((blockIdx.x - 1024) * 512 + tid) * 4;
        int4   r4 = *reinterpret_cast<const int4*>(&erow[base]);
        int4   c4 = *reinterpret_cast<const int4*>(&ecol[base]);
        float4 v4 = *reinterpret_cast<const float4*>(&eval[base]);
        int p0 = atomicAdd(&g_cnt[r4.x], 1);
        int p1 = atomicAdd(&g_cnt[r4.y], 1);
        int p2 = atomicAdd(&g_cnt[r4.z], 1);
        int p3 = atomicAdd(&g_cnt[r4.w], 1);
        g_ell[r4.x * ELL_S + p0] = make_int2(c4.x, __float_as_int(v4.x));
        g_ell[r4.y * ELL_S + p1] = make_int2(c4.y, __float_as_int(v4.y));
        g_ell[r4.z * ELL_S + p2] = make_int2(c4.z, __float_as_int(v4.z));
        g_ell[r4.w * ELL_S + p3] = make_int2(c4.w, __float_as_int(v4.w));
        return;
    }

    // ---- xw0: 16 warps; warp w owns k-slice [32w,32w+32), W pre-packed f32x2
    __shared__ float sbuf[8 * 512];     // 16KB: X tile, then partials
    const int lane = tid & 31;
    const int wid  = tid >> 5;
    const int row0 = blockIdx.x * 8;
    const int kw   = wid * 32;

    ull wp[16];
    #pragma unroll
    for (int kk = 0; kk < 16; kk++)
        wp[kk] = pack2(W0[(size_t)(kw + 2 * kk)     * H1 + lane],
                       W0[(size_t)(kw + 2 * kk + 1) * H1 + lane]);

    {
        const float4* X4 = reinterpret_cast<const float4*>(X + (size_t)row0 * D_IN);
        float4* S4 = reinterpret_cast<float4*>(sbuf);
        S4[tid]       = X4[tid];
        S4[tid + 512] = X4[tid + 512];
    }
    __syncthreads();

    ull acc2[8];
    #pragma unroll
    for (int r = 0; r < 8; r++) acc2[r] = 0ull;

    #pragma unroll
    for (int kk4 = 0; kk4 < 8; kk4++) {
        const int k = kw + kk4 * 4;
        const ull w01 = wp[kk4 * 2];
        const ull w23 = wp[kk4 * 2 + 1];
        #pragma unroll
        for (int r = 0; r < 8; r++) {
            ulonglong2 xq = *reinterpret_cast<const ulonglong2*>(&sbuf[r * 512 + k]);
            acc2[r] = ffma2(xq.x, w01, acc2[r]);
            acc2[r] = ffma2(xq.y, w23, acc2[r]);
        }
    }
    __syncthreads();
    #pragma unroll
    for (int r = 0; r < 8; r++)
        sbuf[wid * 256 + r * 32 + lane] = hadd2(acc2[r]);
    __syncthreads();

    if (tid < 256) {
        int r = tid >> 5, c = tid & 31;
        float s = 0.f;
        #pragma unroll
        for (int w = 0; w < 16; w++)
            s += sbuf[w * 256 + r * 32 + c];
        g_xw0[(size_t)(row0 + r) * H1 + c] = s;
    }
}

// ===================== K2: fused spmm1 + relu + @W1 =====================
// warp per row, HALF-warp per edge: lane = (edge parity, column pair).
__global__ void k_spmm1_hw1(const float* __restrict__ W1) {
    __shared__ float sW1[H1][H2];
    __shared__ float sH[8][H1];
    const int tid  = threadIdx.x;
    const int lane = tid & 31;
    const int wid  = tid >> 5;
    const int half = lane >> 4;        // edge parity
    const int cp   = lane & 15;        // column pair (2 of H1=32)
    for (int idx = tid; idx < H1 * H2; idx += 256)
        sW1[idx >> 4][idx & 15] = W1[idx];
    __syncthreads();

    const int row = blockIdx.x * 8 + wid;
    const int beg = row * ELL_S;
    const int end = beg + g_cnt[row];
    ull acc = 0ull;
    for (int e0 = beg; e0 < end; e0 += 32) {
        int ee = e0 + lane;
        int2 ed = (ee < end) ? g_ell[ee] : make_int2(0, 0);  // zero-filled tail
        #pragma unroll
        for (int j = 0; j < 16; j++) {
            int jj = j * 2 + half;
            int   cj = __shfl_sync(0xFFFFFFFFu, ed.x, jj);
            float vj = __int_as_float(__shfl_sync(0xFFFFFFFFu, ed.y, jj));
            ull xv = *reinterpret_cast<const ull*>(&g_xw0[cj * H1 + 2 * cp]);
            acc = ffma2(pack2(vj, vj), xv, acc);
        }
    }
    float2 f = u2f2(acc);
    f.x += __shfl_xor_sync(0xFFFFFFFFu, f.x, 16);
    f.y += __shfl_xor_sync(0xFFFFFFFFu, f.y, 16);
    if (lane < 16) {
        sH[wid][2 * cp + 0] = fmaxf(f.x, 0.0f);
        sH[wid][2 * cp + 1] = fmaxf(f.y, 0.0f);
    }
    __syncwarp();
    if (lane < H2) {
        float o = 0.f;
        #pragma unroll
        for (int k = 0; k < H1; k++)
            o = fmaf(sH[wid][k], sW1[k][lane], o);
        g_hw1[row * H2 + lane] = o;
    }
}

// ===================== K3: spmm2: warp per row, QUARTER-warp per edge =====================
__global__ void k_spmm2() {
    const int tid  = threadIdx.x;
    const int lane = tid & 31;
    const int wid  = tid >> 5;
    const int q    = lane >> 3;        // edge phase 0..3
    const int cp   = lane & 7;         // column pair (2 of H2=16)

    const int row = blockIdx.x * 8 + wid;
    const int beg = row * ELL_S;
    const int end = beg + g_cnt[row];
    ull acc = 0ull;
    for (int e0 = beg; e0 < end; e0 += 32) {
        int ee = e0 + lane;
        int2 ed = (ee < end) ? g_ell[ee] : make_int2(0, 0);  // zero-filled tail
        #pragma unroll
        for (int j = 0; j < 8; j++) {
            int jj = j * 4 + q;
            int   cj = __shfl_sync(0xFFFFFFFFu, ed.x, jj);
            float vj = __int_as_float(__shfl_sync(0xFFFFFFFFu, ed.y, jj));
            ull hv = *reinterpret_cast<const ull*>(&g_hw1[cj * H2 + 2 * cp]);
            acc = ffma2(pack2(vj, vj), hv, acc);
        }
    }
    float2 f = u2f2(acc);
    f.x += __shfl_xor_sync(0xFFFFFFFFu, f.x, 8);
    f.y += __shfl_xor_sync(0xFFFFFFFFu, f.y, 8);
    f.x += __shfl_xor_sync(0xFFFFFFFFu, f.x, 16);
    f.y += __shfl_xor_sync(0xFFFFFFFFu, f.y, 16);
    if (lane < 8)
        *reinterpret_cast<float2*>(&g_mean[row * H2 + 2 * cp]) = f;
}

// ===================== fast sigmoid: single MUFU tanh =====================
// Z >= 0 => x >= 0 => sigmoid(x) = 0.5*tanh(x/2) + 0.5, no cancellation.
__device__ __forceinline__ float fast_sigmoid(float x) {
    float th;
    asm("tanh.approx.f32 %0, %1;" : "=f"(th) : "f"(x * 0.5f));
    return fmaf(th, 0.5f, 0.5f);
}

// ===================== K4: decode A = sigmoid(Z Z^T), triangular 64x64 =====================
// 256 thr, per-thread 4(i)x4(j) -> only 8 ull accumulators; launch_bounds(256,5)
// targets 5 blocks/SM (62.5% occ). Mirror via 2 chunked swizzled smem transposes
// (row stride 72 floats, group g' = ty ^ txl -> conflict-free STS.128 phases).
__global__ __launch_bounds__(256, 5) void k_decode(float* __restrict__ out) {
    __shared__ float smem[2368];        // load: sA[16][68]|sB[16][68]; mirror: 32x72
    float* sA = smem;                   // [k][i-row], stride 68
    float* sB = smem + 16 * 68;

    const int t   = blockIdx.x;
    const int tid = threadIdx.x;

    // re-zero g_cnt for the next graph replay (dead by now)
    if (t < 32) g_cnt[t * 256 + tid] = 0;

    // t -> (bi, bj) on 128-tile triangle
    int i = (int)((sqrtf(8.0f * (float)t + 1.0f) - 1.0f) * 0.5f);
    int j = t - ((i * (i + 1)) >> 1);
    if (j < 0)  { i--; j = t - ((i * (i + 1)) >> 1); }
    if (j > i)  { i++; j = t - ((i * (i + 1)) >> 1); }
    const int bi = j, bj = i;
    const int i0 = bi * 64, j0 = bj * 64;

    #pragma unroll
    for (int it = 0; it < 4; it++) {
        int idx = tid + it * 256;       // 64*16 elements each
        int r = idx >> 4, c = idx & 15;
        sA[c * 68 + r] = fmaxf(g_mean[(i0 + r) * H2 + c], 1e-32f);
        sB[c * 68 + r] = fmaxf(g_mean[(j0 + r) * H2 + c], 1e-32f);
    }
    __syncthreads();

    const int tx = tid & 15;            // 4 j-cols each (tx*4)
    const int ty = tid >> 4;            // 4 i-rows each (ty*4)
    ull acc2[2][4];                     // [i-pair][j]
    #pragma unroll
    for (int p = 0; p < 2; p++)
        #pragma unroll
        for (int jj = 0; jj < 4; jj++) acc2[p][jj] = 0ull;

    #pragma unroll
    for (int k = 0; k < H2; k++) {
        ulonglong2 aq = *reinterpret_cast<const ulonglong2*>(&sA[k * 68 + ty * 4]);
        float4 bv = *reinterpret_cast<const float4*>(&sB[k * 68 + tx * 4]);
        ull bp[4] = {pack2(bv.x, bv.x), pack2(bv.y, bv.y),
                     pack2(bv.z, bv.z), pack2(bv.w, bv.w)};
        #pragma unroll
        for (int jj = 0; jj < 4; jj++) {
            acc2[0][jj] = ffma2(aq.x, bp[jj], acc2[0][jj]);
            acc2[1][jj] = ffma2(aq.y, bp[jj], acc2[1][jj]);
        }
    }

    // sigmoid in place
    #pragma unroll
    for (int p = 0; p < 2; p++)
        #pragma unroll
        for (int jj = 0; jj < 4; jj++) {
            float2 f = u2f2(acc2[p][jj]);
            acc2[p][jj] = pack2(fast_sigmoid(f.x), fast_sigmoid(f.y));
        }

    // normal tile (bi,bj): 4 STG.128, each warp covers 2 rows x 256B
    #pragma unroll
    for (int p = 0; p < 2; p++) {
        float2 c0 = u2f2(acc2[p][0]);
        float2 c1 = u2f2(acc2[p][1]);
        float2 c2 = u2f2(acc2[p][2]);
        float2 c3 = u2f2(acc2[p][3]);
        float4 o0 = {c0.x, c1.x, c2.x, c3.x};
        float4 o1 = {c0.y, c1.y, c2.y, c3.y};
        int gi = i0 + ty * 4 + 2 * p;
        __stcs(reinterpret_cast<float4*>(out + (size_t)gi       * N_NODES + j0 + tx * 4), o0);
        __stcs(reinterpret_cast<float4*>(out + (size_t)(gi + 1) * N_NODES + j0 + tx * 4), o1);
    }

    // mirror tile (bj,bi): 2 chunks of 32 j-rows, swizzled transpose (stride 72)
    if (bi != bj) {
        #pragma unroll 1
        for (int c = 0; c < 2; c++) {
            __syncthreads();            // prior smem readers / copy-out done
            if ((tx >> 3) == c) {
                int txl = tx & 7;
                int g   = ty ^ txl;     // swizzled float4-group (0..15)
                #pragma unroll
                for (int jj = 0; jj < 4; jj++) {
                    int row = txl * 4 + jj;
                    float2 f0 = u2f2(acc2[0][jj]);
                    float2 f1 = u2f2(acc2[1][jj]);
                    float4 v = {f0.x, f0.y, f1.x, f1.y};   // i = ty*4..ty*4+3
                    *reinterpret_cast<float4*>(&smem[row * 72 + g * 4]) = v;
                }
            }
            __syncthreads();
            #pragma unroll
            for (int it = 0; it < 2; it++) {
                int idx = tid + it * 256;
                int r  = idx >> 4;      // 0..31
                int c4 = idx & 15;      // 0..15
                int g  = c4 ^ ((r >> 2) & 7);   // unswizzle
                float4 v = *reinterpret_cast<const float4*>(&smem[r * 72 + c4 * 4]);
                __stcs(reinterpret_cast<float4*>(
                    out + (size_t)(j0 + c * 32 + r) * N_NODES + i0 + g * 4), v);
            }
        }
    }
}

extern "C" void kernel_launch(void* const* d_in, const int* in_sizes, int n_in,
                              void* d_out, int out_size) {
    const float* X    = (const float*)d_in[0];
    const int*   erow = (const int*)  d_in[1];
    const int*   ecol = (const int*)  d_in[2];
    const float* ev   = (const float*)d_in[3];
    const float* W0   = (const float*)d_in[4];
    const float* W1   = (const float*)d_in[5];
    // d_in[6] (W2) unused: std branch is dead in eval (Z = mean)
    float* out = (float*)d_out;

    k_phase1  <<<1024 + 128, 512>>>(X, W0, erow, ecol, ev);   // xw0 ∥ scatter
    k_spmm1_hw1<<<N_NODES / 8, 256>>>(W1);
    k_spmm2   <<<N_NODES / 8, 256>>>();
    const int NT = 128 * 129 / 2;   // 8256 triangular 64x64 tiles
    k_decode  <<<NT, 256>>>(out);
}

// round 15
// speedup vs baseline: 2.6198x; 1.0030x over previous
#include <cuda_runtime.h>
#include <cuda_bf16.h>

#define N_NODES 8192
#define D_IN    512
#define H1      32
#define H2      16
#define E_EDGES 262144
#define ELL_S   96            // padded row stride; deg ~ Binom(E,1/N): mean 32, sigma 5.7

typedef unsigned long long ull;

// -------- device-global scratch (no allocation allowed) --------
__device__ float g_xw0 [N_NODES * H1];     // X @ W0
__device__ float g_hw1 [N_NODES * H2];     // relu(spmm1) @ W1
__device__ float g_mean[N_NODES * H2];     // spmm2 result
__device__ int   g_cnt [N_NODES];          // per-row degree/cursor (re-zeroed in spmm2)
__device__ int2  g_ell [N_NODES * ELL_S];  // padded (col, val bits) rows

// packed fp32x2 helpers (sm_103a FFMA2, PTX-only)
__device__ __forceinline__ ull ffma2(ull a, ull b, ull c) {
    ull d;
    asm("fma.rn.f32x2 %0, %1, %2, %3;" : "=l"(d) : "l"(a), "l"(b), "l"(c));
    return d;
}
__device__ __forceinline__ ull pack2(float lo, float hi) {
    ull d;
    asm("mov.b64 %0, {%1, %2};" : "=l"(d) : "r"(__float_as_uint(lo)), "r"(__float_as_uint(hi)));
    return d;
}
__device__ __forceinline__ float2 u2f2(ull p) {
    float2 f;
    asm("mov.b64 {%0, %1}, %2;" : "=f"(f.x), "=f"(f.y) : "l"(p));
    return f;
}
__device__ __forceinline__ float hadd2(ull p) {
    float2 f = u2f2(p);
    return f.x + f.y;
}

// ===================== K1 (fused): xw0 GEMM + ELL scatter =====================
// xw0 path processes its 32-wide k-slice in TWO 16-wide halves so the live W
// slice is wp[8] (16 regs) instead of wp[16] (32 regs): no spills under the
// regs<=40 cap from launch_bounds(512,3). W0 is L2-resident; re-read is free.
__global__ __launch_bounds__(512, 3) void k_phase1(const float* __restrict__ X,
                                                   const float* __restrict__ W0,
                                                   const int* __restrict__ erow,
                                                   const int* __restrict__ ecol,
                                                   const float* __restrict__ eval) {
    const int tid = threadIdx.x;

    if (blockIdx.x >= 1024) {
        // ---- ELL scatter: 4 edges/thread, 4 independent cursor-atomic chains
        int base = ((blockIdx.x - 1024) * 512 + tid) * 4;
        int4   r4 = *reinterpret_cast<const int4*>(&erow[base]);
        int4   c4 = *reinterpret_cast<const int4*>(&ecol[base]);
        float4 v4 = *reinterpret_cast<const float4*>(&eval[base]);
        int p0 = atomicAdd(&g_cnt[r4.x], 1);
        int p1 = atomicAdd(&g_cnt[r4.y], 1);
        int p2 = atomicAdd(&g_cnt[r4.z], 1);
        int p3 = atomicAdd(&g_cnt[r4.w], 1);
        g_ell[r4.x * ELL_S + p0] = make_int2(c4.x, __float_as_int(v4.x));
        g_ell[r4.y * ELL_S + p1] = make_int2(c4.y, __float_as_int(v4.y));
        g_ell[r4.z * ELL_S + p2] = make_int2(c4.z, __float_as_int(v4.z));
        g_ell[r4.w * ELL_S + p3] = make_int2(c4.w, __float_as_int(v4.w));
        return;
    }

    // ---- xw0: 16 warps; warp w owns k-slice [32w, 32w+32)
    __shared__ float sbuf[8 * 512];     // 16KB: X tile, then partials
    const int lane = tid & 31;
    const int wid  = tid >> 5;
    const int row0 = blockIdx.x * 8;
    const int kw   = wid * 32;

    {
        const float4* X4 = reinterpret_cast<const float4*>(X + (size_t)row0 * D_IN);
        float4* S4 = reinterpret_cast<float4*>(sbuf);
        S4[tid]       = X4[tid];
        S4[tid + 512] = X4[tid + 512];
    }
    __syncthreads();

    ull acc2[8];
    #pragma unroll
    for (int r = 0; r < 8; r++) acc2[r] = 0ull;

    #pragma unroll
    for (int h = 0; h < 2; h++) {
        const int kh = kw + h * 16;
        ull wp[8];                      // 16 regs live (vs 32 before) -> no spills
        #pragma unroll
        for (int kk = 0; kk < 8; kk++)
            wp[kk] = pack2(W0[(size_t)(kh + 2 * kk)     * H1 + lane],
                           W0[(size_t)(kh + 2 * kk + 1) * H1 + lane]);
        #pragma unroll
        for (int kk4 = 0; kk4 < 4; kk4++) {
            const int k = kh + kk4 * 4;
            const ull w01 = wp[kk4 * 2];
            const ull w23 = wp[kk4 * 2 + 1];
            #pragma unroll
            for (int r = 0; r < 8; r++) {
                ulonglong2 xq = *reinterpret_cast<const ulonglong2*>(&sbuf[r * 512 + k]);
                acc2[r] = ffma2(xq.x, w01, acc2[r]);
                acc2[r] = ffma2(xq.y, w23, acc2[r]);
            }
        }
    }
    __syncthreads();
    #pragma unroll
    for (int r = 0; r < 8; r++)
        sbuf[wid * 256 + r * 32 + lane] = hadd2(acc2[r]);
    __syncthreads();

    if (tid < 256) {
        int r = tid >> 5, c = tid & 31;
        float s = 0.f;
        #pragma unroll
        for (int w = 0; w < 16; w++)
            s += sbuf[w * 256 + r * 32 + c];
        g_xw0[(size_t)(row0 + r) * H1 + c] = s;
    }
}

// ===================== K2: fused spmm1 + relu + @W1 =====================
// warp per row, HALF-warp per edge: lane = (edge parity, column pair).
__global__ void k_spmm1_hw1(const float* __restrict__ W1) {
    __shared__ float sW1[H1][H2];
    __shared__ float sH[8][H1];
    const int tid  = threadIdx.x;
    const int lane = tid & 31;
    const int wid  = tid >> 5;
    const int half = lane >> 4;        // edge parity
    const int cp   = lane & 15;        // column pair (2 of H1=32)
    for (int idx = tid; idx < H1 * H2; idx += 256)
        sW1[idx >> 4][idx & 15] = W1[idx];
    __syncthreads();

    const int row = blockIdx.x * 8 + wid;
    const int beg = row * ELL_S;
    const int end = beg + g_cnt[row];
    ull acc = 0ull;
    for (int e0 = beg; e0 < end; e0 += 32) {
        int ee = e0 + lane;
        int2 ed = (ee < end) ? g_ell[ee] : make_int2(0, 0);  // zero-filled tail
        #pragma unroll
        for (int j = 0; j < 16; j++) {
            int jj = j * 2 + half;
            int   cj = __shfl_sync(0xFFFFFFFFu, ed.x, jj);
            float vj = __int_as_float(__shfl_sync(0xFFFFFFFFu, ed.y, jj));
            ull xv = *reinterpret_cast<const ull*>(&g_xw0[cj * H1 + 2 * cp]);
            acc = ffma2(pack2(vj, vj), xv, acc);
        }
    }
    float2 f = u2f2(acc);
    f.x += __shfl_xor_sync(0xFFFFFFFFu, f.x, 16);
    f.y += __shfl_xor_sync(0xFFFFFFFFu, f.y, 16);
    if (lane < 16) {
        sH[wid][2 * cp + 0] = fmaxf(f.x, 0.0f);
        sH[wid][2 * cp + 1] = fmaxf(f.y, 0.0f);
    }
    __syncwarp();
    if (lane < H2) {
        float o = 0.f;
        #pragma unroll
        for (int k = 0; k < H1; k++)
            o = fmaf(sH[wid][k], sW1[k][lane], o);
        g_hw1[row * H2 + lane] = o;
    }
}

// ===================== K3: spmm2: warp per row, QUARTER-warp per edge =====================
__global__ void k_spmm2() {
    const int tid  = threadIdx.x;
    const int lane = tid & 31;
    const int wid  = tid >> 5;
    const int q    = lane >> 3;        // edge phase 0..3
    const int cp   = lane & 7;         // column pair (2 of H2=16)

    const int row = blockIdx.x * 8 + wid;
    const int beg = row * ELL_S;
    const int end = beg + g_cnt[row];
    ull acc = 0ull;
    for (int e0 = beg; e0 < end; e0 += 32) {
        int ee = e0 + lane;
        int2 ed = (ee < end) ? g_ell[ee] : make_int2(0, 0);  // zero-filled tail
        #pragma unroll
        for (int j = 0; j < 8; j++) {
            int jj = j * 4 + q;
            int   cj = __shfl_sync(0xFFFFFFFFu, ed.x, jj);
            float vj = __int_as_float(__shfl_sync(0xFFFFFFFFu, ed.y, jj));
            ull hv = *reinterpret_cast<const ull*>(&g_hw1[cj * H2 + 2 * cp]);
            acc = ffma2(pack2(vj, vj), hv, acc);
        }
    }
    float2 f = u2f2(acc);
    f.x += __shfl_xor_sync(0xFFFFFFFFu, f.x, 8);
    f.y += __shfl_xor_sync(0xFFFFFFFFu, f.y, 8);
    f.x += __shfl_xor_sync(0xFFFFFFFFu, f.x, 16);
    f.y += __shfl_xor_sync(0xFFFFFFFFu, f.y, 16);
    if (lane < 8)
        *reinterpret_cast<float2*>(&g_mean[row * H2 + 2 * cp]) = f;

    // g_cnt for this row is dead now: re-zero for the next graph replay
    // (row < N_NODES always; one lane per warp)
    if (lane == 0) g_cnt[row] = 0;
}

// ===================== fast sigmoid: single MUFU tanh =====================
// Z >= 0 => x >= 0 => sigmoid(x) = 0.5*tanh(x/2) + 0.5, no cancellation.
__device__ __forceinline__ float fast_sigmoid(float x) {
    float th;
    asm("tanh.approx.f32 %0, %1;" : "=f"(th) : "f"(x * 0.5f));
    return fmaf(th, 0.5f, 0.5f);
}

// ===================== K4: decode A = sigmoid(Z Z^T), triangular 64x64 =====================
// 256 thr, per-thread 4(i)x4(j); launch_bounds(256,5): 5 blocks/SM. Mirror via
// 2 chunked swizzled smem transposes (stride 72, g' = ty ^ txl, conflict-free).
__global__ __launch_bounds__(256, 5) void k_decode(float* __restrict__ out) {
    __shared__ float smem[2368];        // load: sA[16][68]|sB[16][68]; mirror: 32x72
    float* sA = smem;                   // [k][i-row], stride 68
    float* sB = smem + 16 * 68;

    const int t   = blockIdx.x;
    const int tid = threadIdx.x;

    // t -> (bi, bj) on 128-tile triangle
    int i = (int)((sqrtf(8.0f * (float)t + 1.0f) - 1.0f) * 0.5f);
    int j = t - ((i * (i + 1)) >> 1);
    if (j < 0)  { i--; j = t - ((i * (i + 1)) >> 1); }
    if (j > i)  { i++; j = t - ((i * (i + 1)) >> 1); }
    const int bi = j, bj = i;
    const int i0 = bi * 64, j0 = bj * 64;

    #pragma unroll
    for (int it = 0; it < 4; it++) {
        int idx = tid + it * 256;       // 64*16 elements each
        int r = idx >> 4, c = idx & 15;
        sA[c * 68 + r] = fmaxf(g_mean[(i0 + r) * H2 + c], 1e-32f);
        sB[c * 68 + r] = fmaxf(g_mean[(j0 + r) * H2 + c], 1e-32f);
    }
    __syncthreads();

    const int tx = tid & 15;            // 4 j-cols each (tx*4)
    const int ty = tid >> 4;            // 4 i-rows each (ty*4)
    ull acc2[2][4];                     // [i-pair][j]
    #pragma unroll
    for (int p = 0; p < 2; p++)
        #pragma unroll
        for (int jj = 0; jj < 4; jj++) acc2[p][jj] = 0ull;

    #pragma unroll
    for (int k = 0; k < H2; k++) {
        ulonglong2 aq = *reinterpret_cast<const ulonglong2*>(&sA[k * 68 + ty * 4]);
        float4 bv = *reinterpret_cast<const float4*>(&sB[k * 68 + tx * 4]);
        ull bp[4] = {pack2(bv.x, bv.x), pack2(bv.y, bv.y),
                     pack2(bv.z, bv.z), pack2(bv.w, bv.w)};
        #pragma unroll
        for (int jj = 0; jj < 4; jj++) {
            acc2[0][jj] = ffma2(aq.x, bp[jj], acc2[0][jj]);
            acc2[1][jj] = ffma2(aq.y, bp[jj], acc2[1][jj]);
        }
    }

    // sigmoid in place
    #pragma unroll
    for (int p = 0; p < 2; p++)
        #pragma unroll
        for (int jj = 0; jj < 4; jj++) {
            float2 f = u2f2(acc2[p][jj]);
            acc2[p][jj] = pack2(fast_sigmoid(f.x), fast_sigmoid(f.y));
        }

    // normal tile (bi,bj): 4 STG.128, each warp covers 2 rows x 256B
    #pragma unroll
    for (int p = 0; p < 2; p++) {
        float2 c0 = u2f2(acc2[p][0]);
        float2 c1 = u2f2(acc2[p][1]);
        float2 c2 = u2f2(acc2[p][2]);
        float2 c3 = u2f2(acc2[p][3]);
        float4 o0 = {c0.x, c1.x, c2.x, c3.x};
        float4 o1 = {c0.y, c1.y, c2.y, c3.y};
        int gi = i0 + ty * 4 + 2 * p;
        __stcs(reinterpret_cast<float4*>(out + (size_t)gi       * N_NODES + j0 + tx * 4), o0);
        __stcs(reinterpret_cast<float4*>(out + (size_t)(gi + 1) * N_NODES + j0 + tx * 4), o1);
    }

    // mirror tile (bj,bi): 2 chunks of 32 j-rows, swizzled transpose (stride 72)
    if (bi != bj) {
        #pragma unroll 1
        for (int c = 0; c < 2; c++) {
            __syncthreads();            // prior smem readers / copy-out done
            if ((tx >> 3) == c) {
                int txl = tx & 7;
                int g   = ty ^ txl;     // swizzled float4-group (0..15)
                #pragma unroll
                for (int jj = 0; jj < 4; jj++) {
                    int row = txl * 4 + jj;
                    float2 f0 = u2f2(acc2[0][jj]);
                    float2 f1 = u2f2(acc2[1][jj]);
                    float4 v = {f0.x, f0.y, f1.x, f1.y};   // i = ty*4..ty*4+3
                    *reinterpret_cast<float4*>(&smem[row * 72 + g * 4]) = v;
                }
            }
            __syncthreads();
            #pragma unroll
            for (int it = 0; it < 2; it++) {
                int idx = tid + it * 256;
                int r  = idx >> 4;      // 0..31
                int c4 = idx & 15;      // 0..15
                int g  = c4 ^ ((r >> 2) & 7);   // unswizzle
                float4 v = *reinterpret_cast<const float4*>(&smem[r * 72 + c4 * 4]);
                __stcs(reinterpret_cast<float4*>(
                    out + (size_t)(j0 + c * 32 + r) * N_NODES + i0 + g * 4), v);
            }
        }
    }
}

extern "C" void kernel_launch(void* const* d_in, const int* in_sizes, int n_in,
                              void* d_out, int out_size) {
    const float* X    = (const float*)d_in[0];
    const int*   erow = (const int*)  d_in[1];
    const int*   ecol = (const int*)  d_in[2];
    const float* ev   = (const float*)d_in[3];
    const float* W0   = (const float*)d_in[4];
    const float* W1   = (const float*)d_in[5];
    // d_in[6] (W2) unused: std branch is dead in eval (Z = mean)
    float* out = (float*)d_out;

    k_phase1  <<<1024 + 128, 512>>>(X, W0, erow, ecol, ev);   // xw0 ∥ scatter
    k_spmm1_hw1<<<N_NODES / 8, 256>>>(W1);
    k_spmm2   <<<N_NODES / 8, 256>>>();
    const int NT = 128 * 129 / 2;   // 8256 triangular 64x64 tiles
    k_decode  <<<NT, 256>>>(out);
}

// round 16
// speedup vs baseline: 2.6796x; 1.0228x over previous
#include <cuda_runtime.h>
#include <cuda_bf16.h>

#define N_NODES 8192
#define D_IN    512
#define H1      32
#define H2      16
#define E_EDGES 262144
#define ELL_S   96            // padded row stride; deg ~ Binom(E,1/N): mean 32, sigma 5.7

typedef unsigned long long ull;

// -------- device-global scratch (no allocation allowed) --------
__device__ float g_xw0 [N_NODES * H1];     // X @ W0
__device__ float g_hw1 [N_NODES * H2];     // relu(spmm1) @ W1
__device__ float g_mean[N_NODES * H2];     // spmm2 result
__device__ int   g_cnt [N_NODES];          // per-row degree/cursor (re-zeroed in spmm2)
__device__ int2  g_ell [N_NODES * ELL_S];  // padded (col, val bits) rows

// packed fp32x2 helpers (sm_103a FFMA2, PTX-only)
__device__ __forceinline__ ull ffma2(ull a, ull b, ull c) {
    ull d;
    asm("fma.rn.f32x2 %0, %1, %2, %3;" : "=l"(d) : "l"(a), "l"(b), "l"(c));
    return d;
}
__device__ __forceinline__ ull pack2(float lo, float hi) {
    ull d;
    asm("mov.b64 %0, {%1, %2};" : "=l"(d) : "r"(__float_as_uint(lo)), "r"(__float_as_uint(hi)));
    return d;
}
__device__ __forceinline__ float2 u2f2(ull p) {
    float2 f;
    asm("mov.b64 {%0, %1}, %2;" : "=f"(f.x), "=f"(f.y) : "l"(p));
    return f;
}
__device__ __forceinline__ float hadd2(ull p) {
    float2 f = u2f2(p);
    return f.x + f.y;
}

// ===================== K1 (fused): xw0 GEMM + ELL scatter =====================
__global__ __launch_bounds__(512, 3) void k_phase1(const float* __restrict__ X,
                                                   const float* __restrict__ W0,
                                                   const int* __restrict__ erow,
                                                   const int* __restrict__ ecol,
                                                   const float* __restrict__ eval) {
    const int tid = threadIdx.x;

    if (blockIdx.x >= 1024) {
        // ---- ELL scatter: 4 edges/thread, 4 independent cursor-atomic chains
        int base = ((blockIdx.x - 1024) * 512 + tid) * 4;
        int4   r4 = *reinterpret_cast<const int4*>(&erow[base]);
        int4   c4 = *reinterpret_cast<const int4*>(&ecol[base]);
        float4 v4 = *reinterpret_cast<const float4*>(&eval[base]);
        int p0 = atomicAdd(&g_cnt[r4.x], 1);
        int p1 = atomicAdd(&g_cnt[r4.y], 1);
        int p2 = atomicAdd(&g_cnt[r4.z], 1);
        int p3 = atomicAdd(&g_cnt[r4.w], 1);
        g_ell[r4.x * ELL_S + p0] = make_int2(c4.x, __float_as_int(v4.x));
        g_ell[r4.y * ELL_S + p1] = make_int2(c4.y, __float_as_int(v4.y));
        g_ell[r4.z * ELL_S + p2] = make_int2(c4.z, __float_as_int(v4.z));
        g_ell[r4.w * ELL_S + p3] = make_int2(c4.w, __float_as_int(v4.w));
        return;
    }

    // ---- xw0: 16 warps; warp w owns k-slice [32w, 32w+32)
    __shared__ float sbuf[8 * 512];     // 16KB: X tile, then partials
    const int lane = tid & 31;
    const int wid  = tid >> 5;
    const int row0 = blockIdx.x * 8;
    const int kw   = wid * 32;

    {
        const float4* X4 = reinterpret_cast<const float4*>(X + (size_t)row0 * D_IN);
        float4* S4 = reinterpret_cast<float4*>(sbuf);
        S4[tid]       = X4[tid];
        S4[tid + 512] = X4[tid + 512];
    }
    __syncthreads();

    ull acc2[8];
    #pragma unroll
    for (int r = 0; r < 8; r++) acc2[r] = 0ull;

    #pragma unroll
    for (int h = 0; h < 2; h++) {
        const int kh = kw + h * 16;
        ull wp[8];
        #pragma unroll
        for (int kk = 0; kk < 8; kk++)
            wp[kk] = pack2(W0[(size_t)(kh + 2 * kk)     * H1 + lane],
                           W0[(size_t)(kh + 2 * kk + 1) * H1 + lane]);
        #pragma unroll
        for (int kk4 = 0; kk4 < 4; kk4++) {
            const int k = kh + kk4 * 4;
            const ull w01 = wp[kk4 * 2];
            const ull w23 = wp[kk4 * 2 + 1];
            #pragma unroll
            for (int r = 0; r < 8; r++) {
                ulonglong2 xq = *reinterpret_cast<const ulonglong2*>(&sbuf[r * 512 + k]);
                acc2[r] = ffma2(xq.x, w01, acc2[r]);
                acc2[r] = ffma2(xq.y, w23, acc2[r]);
            }
        }
    }
    __syncthreads();
    #pragma unroll
    for (int r = 0; r < 8; r++)
        sbuf[wid * 256 + r * 32 + lane] = hadd2(acc2[r]);
    __syncthreads();

    if (tid < 256) {
        int r = tid >> 5, c = tid & 31;
        float s = 0.f;
        #pragma unroll
        for (int w = 0; w < 16; w++)
            s += sbuf[w * 256 + r * 32 + c];
        g_xw0[(size_t)(row0 + r) * H1 + c] = s;
    }
}

// ===================== K2: fused spmm1 + relu + @W1 =====================
// warp per row, HALF-warp per edge: lane = (edge parity, column pair).
__global__ void k_spmm1_hw1(const float* __restrict__ W1) {
    __shared__ float sW1[H1][H2];
    __shared__ float sH[8][H1];
    const int tid  = threadIdx.x;
    const int lane = tid & 31;
    const int wid  = tid >> 5;
    const int half = lane >> 4;        // edge parity
    const int cp   = lane & 15;        // column pair (2 of H1=32)
    for (int idx = tid; idx < H1 * H2; idx += 256)
        sW1[idx >> 4][idx & 15] = W1[idx];
    __syncthreads();

    const int row = blockIdx.x * 8 + wid;
    const int beg = row * ELL_S;
    const int end = beg + g_cnt[row];
    ull acc = 0ull;
    for (int e0 = beg; e0 < end; e0 += 32) {
        int ee = e0 + lane;
        int2 ed = (ee < end) ? g_ell[ee] : make_int2(0, 0);  // zero-filled tail
        #pragma unroll
        for (int j = 0; j < 16; j++) {
            int jj = j * 2 + half;
            int   cj = __shfl_sync(0xFFFFFFFFu, ed.x, jj);
            float vj = __int_as_float(__shfl_sync(0xFFFFFFFFu, ed.y, jj));
            ull xv = *reinterpret_cast<const ull*>(&g_xw0[cj * H1 + 2 * cp]);
            acc = ffma2(pack2(vj, vj), xv, acc);
        }
    }
    float2 f = u2f2(acc);
    f.x += __shfl_xor_sync(0xFFFFFFFFu, f.x, 16);
    f.y += __shfl_xor_sync(0xFFFFFFFFu, f.y, 16);
    if (lane < 16) {
        sH[wid][2 * cp + 0] = fmaxf(f.x, 0.0f);
        sH[wid][2 * cp + 1] = fmaxf(f.y, 0.0f);
    }
    __syncwarp();
    if (lane < H2) {
        float o = 0.f;
        #pragma unroll
        for (int k = 0; k < H1; k++)
            o = fmaf(sH[wid][k], sW1[k][lane], o);
        g_hw1[row * H2 + lane] = o;
    }
}

// ===================== K3: spmm2: warp per row, QUARTER-warp per edge =====================
__global__ void k_spmm2() {
    const int tid  = threadIdx.x;
    const int lane = tid & 31;
    const int wid  = tid >> 5;
    const int q    = lane >> 3;        // edge phase 0..3
    const int cp   = lane & 7;         // column pair (2 of H2=16)

    const int row = blockIdx.x * 8 + wid;
    const int beg = row * ELL_S;
    const int end = beg + g_cnt[row];
    ull acc = 0ull;
    for (int e0 = beg; e0 < end; e0 += 32) {
        int ee = e0 + lane;
        int2 ed = (ee < end) ? g_ell[ee] : make_int2(0, 0);  // zero-filled tail
        #pragma unroll
        for (int j = 0; j < 8; j++) {
            int jj = j * 4 + q;
            int   cj = __shfl_sync(0xFFFFFFFFu, ed.x, jj);
            float vj = __int_as_float(__shfl_sync(0xFFFFFFFFu, ed.y, jj));
            ull hv = *reinterpret_cast<const ull*>(&g_hw1[cj * H2 + 2 * cp]);
            acc = ffma2(pack2(vj, vj), hv, acc);
        }
    }
    float2 f = u2f2(acc);
    f.x += __shfl_xor_sync(0xFFFFFFFFu, f.x, 8);
    f.y += __shfl_xor_sync(0xFFFFFFFFu, f.y, 8);
    f.x += __shfl_xor_sync(0xFFFFFFFFu, f.x, 16);
    f.y += __shfl_xor_sync(0xFFFFFFFFu, f.y, 16);
    if (lane < 8)
        *reinterpret_cast<float2*>(&g_mean[row * H2 + 2 * cp]) = f;

    // g_cnt for this row is dead now: re-zero for the next graph replay
    if (lane == 0) g_cnt[row] = 0;
}

// ===================== fast sigmoid: single MUFU tanh =====================
// Z >= 0 => x >= 0 => sigmoid(x) = 0.5*tanh(x/2) + 0.5, no cancellation.
__device__ __forceinline__ float fast_sigmoid(float x) {
    float th;
    asm("tanh.approx.f32 %0, %1;" : "=f"(th) : "f"(x * 0.5f));
    return fmaf(th, 0.5f, 0.5f);
}

// ===================== K4: decode A = sigmoid(Z Z^T), triangular 64x64 =====================
// 256 thr, per-thread 4(i)x4(j); launch_bounds(256,6) pushes to 6 blocks/SM
// (regs <= 42): b packed on the fly (no bp[] temp array), k-loop unroll 8.
__global__ __launch_bounds__(256, 6) void k_decode(float* __restrict__ out) {
    __shared__ float smem[2368];        // load: sA[16][68]|sB[16][68]; mirror: 32x72
    float* sA = smem;                   // [k][i-row], stride 68
    float* sB = smem + 16 * 68;

    const int t   = blockIdx.x;
    const int tid = threadIdx.x;

    // t -> (bi, bj) on 128-tile triangle
    int i = (int)((sqrtf(8.0f * (float)t + 1.0f) - 1.0f) * 0.5f);
    int j = t - ((i * (i + 1)) >> 1);
    if (j < 0)  { i--; j = t - ((i * (i + 1)) >> 1); }
    if (j > i)  { i++; j = t - ((i * (i + 1)) >> 1); }
    const int bi = j, bj = i;
    const int i0 = bi * 64, j0 = bj * 64;

    #pragma unroll
    for (int it = 0; it < 4; it++) {
        int idx = tid + it * 256;       // 64*16 elements each
        int r = idx >> 4, c = idx & 15;
        sA[c * 68 + r] = fmaxf(g_mean[(i0 + r) * H2 + c], 1e-32f);
        sB[c * 68 + r] = fmaxf(g_mean[(j0 + r) * H2 + c], 1e-32f);
    }
    __syncthreads();

    const int tx = tid & 15;            // 4 j-cols each (tx*4)
    const int ty = tid >> 4;            // 4 i-rows each (ty*4)
    ull acc2[2][4];                     // [i-pair][j]
    #pragma unroll
    for (int p = 0; p < 2; p++)
        #pragma unroll
        for (int jj = 0; jj < 4; jj++) acc2[p][jj] = 0ull;

    #pragma unroll 8
    for (int k = 0; k < H2; k++) {
        ulonglong2 aq = *reinterpret_cast<const ulonglong2*>(&sA[k * 68 + ty * 4]);
        float4 bv = *reinterpret_cast<const float4*>(&sB[k * 68 + tx * 4]);
        {
            ull b0 = pack2(bv.x, bv.x);
            acc2[0][0] = ffma2(aq.x, b0, acc2[0][0]);
            acc2[1][0] = ffma2(aq.y, b0, acc2[1][0]);
        }
        {
            ull b1 = pack2(bv.y, bv.y);
            acc2[0][1] = ffma2(aq.x, b1, acc2[0][1]);
            acc2[1][1] = ffma2(aq.y, b1, acc2[1][1]);
        }
        {
            ull b2 = pack2(bv.z, bv.z);
            acc2[0][2] = ffma2(aq.x, b2, acc2[0][2]);
            acc2[1][2] = ffma2(aq.y, b2, acc2[1][2]);
        }
        {
            ull b3 = pack2(bv.w, bv.w);
            acc2[0][3] = ffma2(aq.x, b3, acc2[0][3]);
            acc2[1][3] = ffma2(aq.y, b3, acc2[1][3]);
        }
    }

    // sigmoid in place
    #pragma unroll
    for (int p = 0; p < 2; p++)
        #pragma unroll
        for (int jj = 0; jj < 4; jj++) {
            float2 f = u2f2(acc2[p][jj]);
            acc2[p][jj] = pack2(fast_sigmoid(f.x), fast_sigmoid(f.y));
        }

    // normal tile (bi,bj): 4 STG.128, each warp covers 2 rows x 256B
    #pragma unroll
    for (int p = 0; p < 2; p++) {
        float2 c0 = u2f2(acc2[p][0]);
        float2 c1 = u2f2(acc2[p][1]);
        float2 c2 = u2f2(acc2[p][2]);
        float2 c3 = u2f2(acc2[p][3]);
        float4 o0 = {c0.x, c1.x, c2.x, c3.x};
        float4 o1 = {c0.y, c1.y, c2.y, c3.y};
        int gi = i0 + ty * 4 + 2 * p;
        __stcs(reinterpret_cast<float4*>(out + (size_t)gi       * N_NODES + j0 + tx * 4), o0);
        __stcs(reinterpret_cast<float4*>(out + (size_t)(gi + 1) * N_NODES + j0 + tx * 4), o1);
    }

    // mirror tile (bj,bi): 2 chunks of 32 j-rows, swizzled transpose (stride 72)
    if (bi != bj) {
        #pragma unroll 1
        for (int c = 0; c < 2; c++) {
            __syncthreads();            // prior smem readers / copy-out done
            if ((tx >> 3) == c) {
                int txl = tx & 7;
                int g   = ty ^ txl;     // swizzled float4-group (0..15)
                #pragma unroll
                for (int jj = 0; jj < 4; jj++) {
                    int row = txl * 4 + jj;
                    float2 f0 = u2f2(acc2[0][jj]);
                    float2 f1 = u2f2(acc2[1][jj]);
                    float4 v = {f0.x, f0.y, f1.x, f1.y};   // i = ty*4..ty*4+3
                    *reinterpret_cast<float4*>(&smem[row * 72 + g * 4]) = v;
                }
            }
            __syncthreads();
            #pragma unroll
            for (int it = 0; it < 2; it++) {
                int idx = tid + it * 256;
                int r  = idx >> 4;      // 0..31
                int c4 = idx & 15;      // 0..15
                int g  = c4 ^ ((r >> 2) & 7);   // unswizzle
                float4 v = *reinterpret_cast<const float4*>(&smem[r * 72 + c4 * 4]);
                __stcs(reinterpret_cast<float4*>(
                    out + (size_t)(j0 + c * 32 + r) * N_NODES + i0 + g * 4), v);
            }
        }
    }
}

extern "C" void kernel_launch(void* const* d_in, const int* in_sizes, int n_in,
                              void* d_out, int out_size) {
    const float* X    = (const float*)d_in[0];
    const int*   erow = (const int*)  d_in[1];
    const int*   ecol = (const int*)  d_in[2];
    const float* ev   = (const float*)d_in[3];
    const float* W0   = (const float*)d_in[4];
    const float* W1   = (const float*)d_in[5];
    // d_in[6] (W2) unused: std branch is dead in eval (Z = mean)
    float* out = (float*)d_out;

    k_phase1  <<<1024 + 128, 512>>>(X, W0, erow, ecol, ev);   // xw0 ∥ scatter
    k_spmm1_hw1<<<N_NODES / 8, 256>>>(W1);
    k_spmm2   <<<N_NODES / 8, 256>>>();
    const int NT = 128 * 129 / 2;   // 8256 triangular 64x64 tiles
    k_decode  <<<NT, 256>>>(out);
}

// round 17
// speedup vs baseline: 2.6816x; 1.0008x over previous
#include <cuda_runtime.h>
#include <cuda_bf16.h>

#define N_NODES 8192
#define D_IN    512
#define H1      32
#define H2      16
#define E_EDGES 262144
#define ELL_S   96            // padded row stride; deg ~ Binom(E,1/N): mean 32, sigma 5.7

typedef unsigned long long ull;

// -------- device-global scratch (no allocation allowed) --------
__device__ float g_xw0 [N_NODES * H1];     // X @ W0
__device__ float g_hw1 [N_NODES * H2];     // relu(spmm1) @ W1
__device__ float g_mean[N_NODES * H2];     // spmm2 result
__device__ int   g_cnt [N_NODES];          // per-row degree/cursor (re-zeroed in spmm2)
__device__ int2  g_ell [N_NODES * ELL_S];  // padded (col, val bits) rows

// packed fp32x2 helpers (sm_103a FFMA2, PTX-only)
__device__ __forceinline__ ull ffma2(ull a, ull b, ull c) {
    ull d;
    asm("fma.rn.f32x2 %0, %1, %2, %3;" : "=l"(d) : "l"(a), "l"(b), "l"(c));
    return d;
}
__device__ __forceinline__ ull pack2(float lo, float hi) {
    ull d;
    asm("mov.b64 %0, {%1, %2};" : "=l"(d) : "r"(__float_as_uint(lo)), "r"(__float_as_uint(hi)));
    return d;
}
__device__ __forceinline__ float2 u2f2(ull p) {
    float2 f;
    asm("mov.b64 {%0, %1}, %2;" : "=f"(f.x), "=f"(f.y) : "l"(p));
    return f;
}
__device__ __forceinline__ float hadd2(ull p) {
    float2 f = u2f2(p);
    return f.x + f.y;
}

// ===================== K1 (fused): xw0 GEMM + ELL scatter =====================
// 256-thr blocks. blocks [0,1024): xw0, 8 rows each; 8 warps, warp w owns the
// 64-wide k-slice [64w, 64w+64) processed in four 16-wide chunks (wp[8] live).
// blocks [1024, 1280): ELL scatter, 4 edges/thread.
// Smaller blocks -> 6 blocks/SM -> 1.44 waves (was 2.6 with 512-thr blocks).
__global__ __launch_bounds__(256, 6) void k_phase1(const float* __restrict__ X,
                                                   const float* __restrict__ W0,
                                                   const int* __restrict__ erow,
                                                   const int* __restrict__ ecol,
                                                   const float* __restrict__ eval) {
    const int tid = threadIdx.x;

    if (blockIdx.x >= 1024) {
        // ---- ELL scatter: 4 edges/thread, 4 independent cursor-atomic chains
        int base = ((blockIdx.x - 1024) * 256 + tid) * 4;
        int4   r4 = *reinterpret_cast<const int4*>(&erow[base]);
        int4   c4 = *reinterpret_cast<const int4*>(&ecol[base]);
        float4 v4 = *reinterpret_cast<const float4*>(&eval[base]);
        int p0 = atomicAdd(&g_cnt[r4.x], 1);
        int p1 = atomicAdd(&g_cnt[r4.y], 1);
        int p2 = atomicAdd(&g_cnt[r4.z], 1);
        int p3 = atomicAdd(&g_cnt[r4.w], 1);
        g_ell[r4.x * ELL_S + p0] = make_int2(c4.x, __float_as_int(v4.x));
        g_ell[r4.y * ELL_S + p1] = make_int2(c4.y, __float_as_int(v4.y));
        g_ell[r4.z * ELL_S + p2] = make_int2(c4.z, __float_as_int(v4.z));
        g_ell[r4.w * ELL_S + p3] = make_int2(c4.w, __float_as_int(v4.w));
        return;
    }

    // ---- xw0: 8 warps; warp w owns k-slice [64w, 64w+64)
    __shared__ float sbuf[8 * 512];     // 16KB: X tile, then partials (8KB reused)
    const int lane = tid & 31;
    const int wid  = tid >> 5;
    const int row0 = blockIdx.x * 8;
    const int kw   = wid * 64;

    {
        const float4* X4 = reinterpret_cast<const float4*>(X + (size_t)row0 * D_IN);
        float4* S4 = reinterpret_cast<float4*>(sbuf);
        #pragma unroll
        for (int i = 0; i < 4; i++)
            S4[tid + i * 256] = X4[tid + i * 256];
    }
    __syncthreads();

    ull acc2[8];
    #pragma unroll
    for (int r = 0; r < 8; r++) acc2[r] = 0ull;

    #pragma unroll
    for (int h = 0; h < 4; h++) {
        const int kh = kw + h * 16;
        ull wp[8];                      // only 16 regs of W live at a time
        #pragma unroll
        for (int kk = 0; kk < 8; kk++)
            wp[kk] = pack2(W0[(size_t)(kh + 2 * kk)     * H1 + lane],
                           W0[(size_t)(kh + 2 * kk + 1) * H1 + lane]);
        #pragma unroll
        for (int kk4 = 0; kk4 < 4; kk4++) {
            const int k = kh + kk4 * 4;
            const ull w01 = wp[kk4 * 2];
            const ull w23 = wp[kk4 * 2 + 1];
            #pragma unroll
            for (int r = 0; r < 8; r++) {
                ulonglong2 xq = *reinterpret_cast<const ulonglong2*>(&sbuf[r * 512 + k]);
                acc2[r] = ffma2(xq.x, w01, acc2[r]);
                acc2[r] = ffma2(xq.y, w23, acc2[r]);
            }
        }
    }
    __syncthreads();                    // X reads done; reuse sbuf for partials
    #pragma unroll
    for (int r = 0; r < 8; r++)
        sbuf[wid * 256 + r * 32 + lane] = hadd2(acc2[r]);
    __syncthreads();

    // 256 outputs (8 rows x 32 cols), 8-way reduce
    {
        int r = tid >> 5, c = tid & 31;
        float s = 0.f;
        #pragma unroll
        for (int w = 0; w < 8; w++)
            s += sbuf[w * 256 + r * 32 + c];
        g_xw0[(size_t)(row0 + r) * H1 + c] = s;
    }
}

// ===================== K2: fused spmm1 + relu + @W1 =====================
// warp per row, HALF-warp per edge: lane = (edge parity, column pair).
__global__ void k_spmm1_hw1(const float* __restrict__ W1) {
    __shared__ float sW1[H1][H2];
    __shared__ float sH[8][H1];
    const int tid  = threadIdx.x;
    const int lane = tid & 31;
    const int wid  = tid >> 5;
    const int half = lane >> 4;        // edge parity
    const int cp   = lane & 15;        // column pair (2 of H1=32)
    for (int idx = tid; idx < H1 * H2; idx += 256)
        sW1[idx >> 4][idx & 15] = W1[idx];
    __syncthreads();

    const int row = blockIdx.x * 8 + wid;
    const int beg = row * ELL_S;
    const int end = beg + g_cnt[row];
    ull acc = 0ull;
    for (int e0 = beg; e0 < end; e0 += 32) {
        int ee = e0 + lane;
        int2 ed = (ee < end) ? g_ell[ee] : make_int2(0, 0);  // zero-filled tail
        #pragma unroll
        for (int j = 0; j < 16; j++) {
            int jj = j * 2 + half;
            int   cj = __shfl_sync(0xFFFFFFFFu, ed.x, jj);
            float vj = __int_as_float(__shfl_sync(0xFFFFFFFFu, ed.y, jj));
            ull xv = *reinterpret_cast<const ull*>(&g_xw0[cj * H1 + 2 * cp]);
            acc = ffma2(pack2(vj, vj), xv, acc);
        }
    }
    float2 f = u2f2(acc);
    f.x += __shfl_xor_sync(0xFFFFFFFFu, f.x, 16);
    f.y += __shfl_xor_sync(0xFFFFFFFFu, f.y, 16);
    if (lane < 16) {
        sH[wid][2 * cp + 0] = fmaxf(f.x, 0.0f);
        sH[wid][2 * cp + 1] = fmaxf(f.y, 0.0f);
    }
    __syncwarp();
    if (lane < H2) {
        float o = 0.f;
        #pragma unroll
        for (int k = 0; k < H1; k++)
            o = fmaf(sH[wid][k], sW1[k][lane], o);
        g_hw1[row * H2 + lane] = o;
    }
}

// ===================== K3: spmm2: warp per row, QUARTER-warp per edge =====================
__global__ void k_spmm2() {
    const int tid  = threadIdx.x;
    const int lane = tid & 31;
    const int wid  = tid >> 5;
    const int q    = lane >> 3;        // edge phase 0..3
    const int cp   = lane & 7;         // column pair (2 of H2=16)

    const int row = blockIdx.x * 8 + wid;
    const int beg = row * ELL_S;
    const int end = beg + g_cnt[row];
    ull acc = 0ull;
    for (int e0 = beg; e0 < end; e0 += 32) {
        int ee = e0 + lane;
        int2 ed = (ee < end) ? g_ell[ee] : make_int2(0, 0);  // zero-filled tail
        #pragma unroll
        for (int j = 0; j < 8; j++) {
            int jj = j * 4 + q;
            int   cj = __shfl_sync(0xFFFFFFFFu, ed.x, jj);
            float vj = __int_as_float(__shfl_sync(0xFFFFFFFFu, ed.y, jj));
            ull hv = *reinterpret_cast<const ull*>(&g_hw1[cj * H2 + 2 * cp]);
            acc = ffma2(pack2(vj, vj), hv, acc);
        }
    }
    float2 f = u2f2(acc);
    f.x += __shfl_xor_sync(0xFFFFFFFFu, f.x, 8);
    f.y += __shfl_xor_sync(0xFFFFFFFFu, f.y, 8);
    f.x += __shfl_xor_sync(0xFFFFFFFFu, f.x, 16);
    f.y += __shfl_xor_sync(0xFFFFFFFFu, f.y, 16);
    if (lane < 8)
        *reinterpret_cast<float2*>(&g_mean[row * H2 + 2 * cp]) = f;

    // g_cnt for this row is dead now: re-zero for the next graph replay
    if (lane == 0) g_cnt[row] = 0;
}

// ===================== fast sigmoid: single MUFU tanh =====================
// Z >= 0 => x >= 0 => sigmoid(x) = 0.5*tanh(x/2) + 0.5, no cancellation.
__device__ __forceinline__ float fast_sigmoid(float x) {
    float th;
    asm("tanh.approx.f32 %0, %1;" : "=f"(th) : "f"(x * 0.5f));
    return fmaf(th, 0.5f, 0.5f);
}

// ===================== K4: decode A = sigmoid(Z Z^T), triangular 64x64 =====================
// (unchanged from round 16 — 50.8us, near store floor)
__global__ __launch_bounds__(256, 6) void k_decode(float* __restrict__ out) {
    __shared__ float smem[2368];        // load: sA[16][68]|sB[16][68]; mirror: 32x72
    float* sA = smem;                   // [k][i-row], stride 68
    float* sB = smem + 16 * 68;

    const int t   = blockIdx.x;
    const int tid = threadIdx.x;

    // t -> (bi, bj) on 128-tile triangle
    int i = (int)((sqrtf(8.0f * (float)t + 1.0f) - 1.0f) * 0.5f);
    int j = t - ((i * (i + 1)) >> 1);
    if (j < 0)  { i--; j = t - ((i * (i + 1)) >> 1); }
    if (j > i)  { i++; j = t - ((i * (i + 1)) >> 1); }
    const int bi = j, bj = i;
    const int i0 = bi * 64, j0 = bj * 64;

    #pragma unroll
    for (int it = 0; it < 4; it++) {
        int idx = tid + it * 256;       // 64*16 elements each
        int r = idx >> 4, c = idx & 15;
        sA[c * 68 + r] = fmaxf(g_mean[(i0 + r) * H2 + c], 1e-32f);
        sB[c * 68 + r] = fmaxf(g_mean[(j0 + r) * H2 + c], 1e-32f);
    }
    __syncthreads();

    const int tx = tid & 15;            // 4 j-cols each (tx*4)
    const int ty = tid >> 4;            // 4 i-rows each (ty*4)
    ull acc2[2][4];                     // [i-pair][j]
    #pragma unroll
    for (int p = 0; p < 2; p++)
        #pragma unroll
        for (int jj = 0; jj < 4; jj++) acc2[p][jj] = 0ull;

    #pragma unroll 8
    for (int k = 0; k < H2; k++) {
        ulonglong2 aq = *reinterpret_cast<const ulonglong2*>(&sA[k * 68 + ty * 4]);
        float4 bv = *reinterpret_cast<const float4*>(&sB[k * 68 + tx * 4]);
        {
            ull b0 = pack2(bv.x, bv.x);
            acc2[0][0] = ffma2(aq.x, b0, acc2[0][0]);
            acc2[1][0] = ffma2(aq.y, b0, acc2[1][0]);
        }
        {
            ull b1 = pack2(bv.y, bv.y);
            acc2[0][1] = ffma2(aq.x, b1, acc2[0][1]);
            acc2[1][1] = ffma2(aq.y, b1, acc2[1][1]);
        }
        {
            ull b2 = pack2(bv.z, bv.z);
            acc2[0][2] = ffma2(aq.x, b2, acc2[0][2]);
            acc2[1][2] = ffma2(aq.y, b2, acc2[1][2]);
        }
        {
            ull b3 = pack2(bv.w, bv.w);
            acc2[0][3] = ffma2(aq.x, b3, acc2[0][3]);
            acc2[1][3] = ffma2(aq.y, b3, acc2[1][3]);
        }
    }

    // sigmoid in place
    #pragma unroll
    for (int p = 0; p < 2; p++)
        #pragma unroll
        for (int jj = 0; jj < 4; jj++) {
            float2 f = u2f2(acc2[p][jj]);
            acc2[p][jj] = pack2(fast_sigmoid(f.x), fast_sigmoid(f.y));
        }

    // normal tile (bi,bj): 4 STG.128, each warp covers 2 rows x 256B
    #pragma unroll
    for (int p = 0; p < 2; p++) {
        float2 c0 = u2f2(acc2[p][0]);
        float2 c1 = u2f2(acc2[p][1]);
        float2 c2 = u2f2(acc2[p][2]);
        float2 c3 = u2f2(acc2[p][3]);
        float4 o0 = {c0.x, c1.x, c2.x, c3.x};
        float4 o1 = {c0.y, c1.y, c2.y, c3.y};
        int gi = i0 + ty * 4 + 2 * p;
        __stcs(reinterpret_cast<float4*>(out + (size_t)gi       * N_NODES + j0 + tx * 4), o0);
        __stcs(reinterpret_cast<float4*>(out + (size_t)(gi + 1) * N_NODES + j0 + tx * 4), o1);
    }

    // mirror tile (bj,bi): 2 chunks of 32 j-rows, swizzled transpose (stride 72)
    if (bi != bj) {
        #pragma unroll 1
        for (int c = 0; c < 2; c++) {
            __syncthreads();            // prior smem readers / copy-out done
            if ((tx >> 3) == c) {
                int txl = tx & 7;
                int g   = ty ^ txl;     // swizzled float4-group (0..15)
                #pragma unroll
                for (int jj = 0; jj < 4; jj++) {
                    int row = txl * 4 + jj;
                    float2 f0 = u2f2(acc2[0][jj]);
                    float2 f1 = u2f2(acc2[1][jj]);
                    float4 v = {f0.x, f0.y, f1.x, f1.y};   // i = ty*4..ty*4+3
                    *reinterpret_cast<float4*>(&smem[row * 72 + g * 4]) = v;
                }
            }
            __syncthreads();
            #pragma unroll
            for (int it = 0; it < 2; it++) {
                int idx = tid + it * 256;
                int r  = idx >> 4;      // 0..31
                int c4 = idx & 15;      // 0..15
                int g  = c4 ^ ((r >> 2) & 7);   // unswizzle
                float4 v = *reinterpret_cast<const float4*>(&smem[r * 72 + c4 * 4]);
                __stcs(reinterpret_cast<float4*>(
                    out + (size_t)(j0 + c * 32 + r) * N_NODES + i0 + g * 4), v);
            }
        }
    }
}

extern "C" void kernel_launch(void* const* d_in, const int* in_sizes, int n_in,
                              void* d_out, int out_size) {
    const float* X    = (const float*)d_in[0];
    const int*   erow = (const int*)  d_in[1];
    const int*   ecol = (const int*)  d_in[2];
    const float* ev   = (const float*)d_in[3];
    const float* W0   = (const float*)d_in[4];
    const float* W1   = (const float*)d_in[5];
    // d_in[6] (W2) unused: std branch is dead in eval (Z = mean)
    float* out = (float*)d_out;

    k_phase1  <<<1024 + 256, 256>>>(X, W0, erow, ecol, ev);   // xw0 ∥ scatter
    k_spmm1_hw1<<<N_NODES / 8, 256>>>(W1);
    k_spmm2   <<<N_NODES / 8, 256>>>();
    const int NT = 128 * 129 / 2;   // 8256 triangular 64x64 tiles
    k_decode  <<<NT, 256>>>(out);
}